// round 3
// baseline (speedup 1.0000x reference)
#include <cuda_runtime.h>
#include <cuda_fp16.h>
#include <cstdint>

#define PP 2048
#define VV 32000
#define DD 100
#define NT1 256

// ---- scratch (static device arrays; no dynamic allocation allowed) ----
__device__ __align__(16) __half g_wscr[(size_t)PP * VV];  // exp(z - m2), fp16
__device__ float g_invZ2[PP];
__device__ float g_ent[PP];
__device__ int   g_need[PP];   // masked && safe -> row gets GEMM result

// -log(u + 1e-20), accurate near u==1 (where __logf's absolute error would
// corrupt the gumbel tail / argmax). Series uses exact d = 1-u for u >= 0.75.
__device__ __forceinline__ float neglog_u(float u) {
    float ue = u + 1e-20f;
    float d = 1.0f - ue;  // exact for ue in [0.5, 1]
    float s = d * (1.0f + d * (0.5f + d * (0.33333333f + d * (0.25f + d * (0.2f
             + d * (0.16666667f + d * (0.14285714f + d * (0.125f
             + d * 0.11111111f))))))));
    float l = -__logf(ue);
    return (ue >= 0.75f) ? s : l;
}

__device__ __forceinline__ float gumbel_g(float u) {
    return -__logf(neglog_u(u) + 1e-20f);
}

// ================= kernel 1: per-row stats ====================
__global__ void k_stats(const float* __restrict__ logits,
                        const float* __restrict__ gumb,
                        const int*   __restrict__ inp_word,
                        const int*   __restrict__ obf_mask,
                        const float* __restrict__ W,
                        float* __restrict__ out)
{
    const int pos = blockIdx.x;
    const int tid = threadIdx.x;
    float* out_word = out;
    float* out_emb  = out + PP;
    const int iw = inp_word[pos];
    const int mk = obf_mask[pos];

    if (!mk) {
        if (tid == 0) { out_word[pos] = (float)iw; g_ent[pos] = 0.0f; g_need[pos] = 0; }
        for (int d = tid; d < DD; d += NT1)
            out_emb[(size_t)pos * DD + d] = W[(size_t)iw * DD + d];
        return;
    }

    const float* xr = logits + (size_t)pos * VV;
    const float* ur = gumb   + (size_t)pos * VV;
    __half* wr = g_wscr + (size_t)pos * VV;

    // ---- pass 1: max(logits), max+argmax(logits+g) ----
    float m1 = -3.0e38f, mz = -3.0e38f;
    int ai = 0;
    for (int i = tid; i < VV; i += NT1) {
        float x = xr[i];
        float z = x + gumbel_g(ur[i]);
        m1 = fmaxf(m1, x);
        if (z > mz) { mz = z; ai = i; }
    }
    const unsigned FULL = 0xffffffffu;
    #pragma unroll
    for (int off = 16; off; off >>= 1) {
        m1 = fmaxf(m1, __shfl_down_sync(FULL, m1, off));
        float oz = __shfl_down_sync(FULL, mz, off);
        int   oi = __shfl_down_sync(FULL, ai, off);
        if (oz > mz || (oz == mz && oi < ai)) { mz = oz; ai = oi; }
    }
    __shared__ float sA[NT1/32], sB[NT1/32];
    __shared__ int   sI[NT1/32];
    const int wid = tid >> 5, lane = tid & 31;
    if (lane == 0) { sA[wid] = m1; sB[wid] = mz; sI[wid] = ai; }
    __syncthreads();
    if (tid == 0) {
        #pragma unroll
        for (int w = 1; w < NT1/32; w++) {
            m1 = fmaxf(m1, sA[w]);
            if (sB[w] > mz || (sB[w] == mz && sI[w] < ai)) { mz = sB[w]; ai = sI[w]; }
        }
        sA[0] = m1; sB[0] = mz; sI[0] = ai;
    }
    __syncthreads();
    const float M1 = sA[0], MZ = sB[0];
    const int   AI = sI[0];
    __syncthreads();

    // ---- pass 2: sums; write fp16 weights ----
    float e1 = 0.f, a1 = 0.f, e2 = 0.f;
    for (int i = tid; i < VV; i += NT1) {
        float x = xr[i];
        float t = x - M1;
        float p = __expf(t);
        e1 += p; a1 += p * t;
        float w = __expf(x + gumbel_g(ur[i]) - MZ);
        e2 += w;
        wr[i] = __float2half(w);
    }
    #pragma unroll
    for (int off = 16; off; off >>= 1) {
        e1 += __shfl_down_sync(FULL, e1, off);
        a1 += __shfl_down_sync(FULL, a1, off);
        e2 += __shfl_down_sync(FULL, e2, off);
    }
    __shared__ float sE1[NT1/32], sA1[NT1/32], sE2[NT1/32];
    __shared__ int sSafe;
    if (lane == 0) { sE1[wid] = e1; sA1[wid] = a1; sE2[wid] = e2; }
    __syncthreads();
    if (tid == 0) {
        float E1 = 0.f, A1 = 0.f, E2 = 0.f;
        #pragma unroll
        for (int w = 0; w < NT1/32; w++) { E1 += sE1[w]; A1 += sA1[w]; E2 += sE2[w]; }
        g_ent[pos]   = A1 / E1 - logf(E1);   // sum p*lp
        g_invZ2[pos] = 1.0f / E2;
        int safe = (AI != iw) ? 1 : 0;
        g_need[pos] = safe;
        out_word[pos] = safe ? (float)AI : 0.0f;   // UNK_ID = 0
        sSafe = safe;
    }
    __syncthreads();
    const int safe = sSafe;
    for (int d = tid; d < DD; d += NT1)
        out_emb[(size_t)pos * DD + d] = safe ? 0.0f : W[d];  // zero for atomics, or W[UNK]
}

// ================= kernel 2: TF32 GEMM  emb = (w/Z2) @ W ====================
#define MT 64
#define KT 32
#define NSPLIT 10
#define KSEG (VV / NSPLIT)   // 3200

__device__ __forceinline__ uint32_t f2tf(float f) {
    uint32_t r;
    asm("cvt.rna.tf32.f32 %0, %1;" : "=r"(r) : "f"(f));
    return r;
}

__global__ void __launch_bounds__(128, 1) k_gemm(const float* __restrict__ W,
                                                 float* __restrict__ out)
{
    float* out_emb = out + PP;
    const int rowBase = blockIdx.x * MT;
    const int kBase   = blockIdx.y * KSEG;
    const int tid  = threadIdx.x;
    const int wid  = tid >> 5, lane = tid & 31;
    const int grp  = lane >> 2, tig = lane & 3;

    __shared__ uint32_t As[MT * 36];    // tf32 bits, padded stride 36
    __shared__ uint32_t Bs[KT * 104];   // tf32 bits, padded stride 104

    float c[13][4];
    #pragma unroll
    for (int j = 0; j < 13; j++) { c[j][0]=0.f; c[j][1]=0.f; c[j][2]=0.f; c[j][3]=0.f; }

    const int arow = tid >> 1;
    const int acb  = (tid & 1) << 4;
    const int apos = rowBase + arow;
    const bool nd  = (g_need[apos] != 0);
    const __half* hp = g_wscr + (size_t)apos * VV + kBase + acb;
    if (!nd) {
        #pragma unroll
        for (int j = 0; j < 16; j++) As[arow*36 + acb + j] = 0u;
    }

    for (int kc = 0; kc < KSEG; kc += KT) {
        __syncthreads();
        // W chunk: rows [kBase+kc, +32) are contiguous (row-major [V,100])
        const float* wp = W + (size_t)(kBase + kc) * DD;
        #pragma unroll
        for (int it = 0; it < (KT*DD)/128; it++) {
            int idx = tid + it * 128;
            int kr = idx / DD;
            int d  = idx - kr * DD;
            Bs[kr * 104 + d] = f2tf(wp[idx]);
        }
        // A chunk: fp16 weights -> tf32 bits
        if (nd) {
            const uint4* p4 = (const uint4*)(hp + kc);
            uint4 v0 = p4[0], v1 = p4[1];
            uint32_t* dst = &As[arow*36 + acb];
            const __half2* h0 = (const __half2*)&v0;
            const __half2* h1 = (const __half2*)&v1;
            #pragma unroll
            for (int j = 0; j < 4; j++) {
                float2 f = __half22float2(h0[j]);
                dst[2*j]   = f2tf(f.x);
                dst[2*j+1] = f2tf(f.y);
            }
            #pragma unroll
            for (int j = 0; j < 4; j++) {
                float2 f = __half22float2(h1[j]);
                dst[8+2*j]   = f2tf(f.x);
                dst[8+2*j+1] = f2tf(f.y);
            }
        }
        __syncthreads();
        const int wrow = wid * 16;
        #pragma unroll
        for (int ks = 0; ks < 4; ks++) {
            const int k8 = ks * 8;
            uint32_t a0 = As[(wrow+grp  )*36 + k8 + tig];
            uint32_t a1 = As[(wrow+grp+8)*36 + k8 + tig];
            uint32_t a2 = As[(wrow+grp  )*36 + k8 + tig + 4];
            uint32_t a3 = As[(wrow+grp+8)*36 + k8 + tig + 4];
            #pragma unroll
            for (int j = 0; j < 13; j++) {
                uint32_t b0 = Bs[(k8+tig  )*104 + j*8 + grp];
                uint32_t b1 = Bs[(k8+tig+4)*104 + j*8 + grp];
                asm volatile(
                  "mma.sync.aligned.m16n8k8.row.col.f32.tf32.tf32.f32 "
                  "{%0,%1,%2,%3},{%4,%5,%6,%7},{%8,%9},{%0,%1,%2,%3};"
                  : "+f"(c[j][0]), "+f"(c[j][1]), "+f"(c[j][2]), "+f"(c[j][3])
                  : "r"(a0), "r"(a1), "r"(a2), "r"(a3), "r"(b0), "r"(b1));
            }
        }
    }

    // epilogue: scale by 1/Z2, accumulate (k-split partials) via atomics
    const int r0 = rowBase + wid*16 + grp;
    const int r1 = r0 + 8;
    const float s0 = g_need[r0] ? g_invZ2[r0] : 0.f;
    const float s1 = g_need[r1] ? g_invZ2[r1] : 0.f;
    #pragma unroll
    for (int j = 0; j < 13; j++) {
        int col = j*8 + tig*2;
        if (col < DD) {
            if (s0 != 0.f) atomicAdd(&out_emb[(size_t)r0*DD + col], c[j][0]*s0);
            if (s1 != 0.f) atomicAdd(&out_emb[(size_t)r1*DD + col], c[j][2]*s1);
        }
        if (col + 1 < DD) {
            if (s0 != 0.f) atomicAdd(&out_emb[(size_t)r0*DD + col+1], c[j][1]*s0);
            if (s1 != 0.f) atomicAdd(&out_emb[(size_t)r1*DD + col+1], c[j][3]*s1);
        }
    }
}

// ================= kernel 3: entropy loss reduction ====================
__global__ void k_ent(const int* __restrict__ obf_mask, float* __restrict__ out)
{
    __shared__ float ss[256];
    __shared__ int   sc[256];
    const int tid = threadIdx.x;
    float s = 0.f; int c = 0;
    for (int i = tid; i < PP; i += 256) { s += g_ent[i]; c += obf_mask[i]; }
    ss[tid] = s; sc[tid] = c;
    __syncthreads();
    for (int o = 128; o; o >>= 1) {
        if (tid < o) { ss[tid] += ss[tid + o]; sc[tid] += sc[tid + o]; }
        __syncthreads();
    }
    if (tid == 0) {
        float n = (float)sc[0];
        out[PP + (size_t)PP * DD] = ss[0] / (n * (float)VV);
    }
}

// ================= launch ====================
extern "C" void kernel_launch(void* const* d_in, const int* in_sizes, int n_in,
                              void* d_out, int out_size)
{
    (void)in_sizes; (void)n_in; (void)out_size;
    const float* logits = (const float*)d_in[0];
    const float* gumb   = (const float*)d_in[1];
    const int*   inp    = (const int*)d_in[2];
    const int*   mask   = (const int*)d_in[3];
    const float* W      = (const float*)d_in[4];
    float* out = (float*)d_out;

    k_stats<<<PP, NT1>>>(logits, gumb, inp, mask, W, out);
    dim3 gg(PP / MT, NSPLIT);
    k_gemm<<<gg, 128>>>(W, out);
    k_ent<<<1, 256>>>(mask, out);
}

// round 5
// speedup vs baseline: 1.4621x; 1.4621x over previous
#include <cuda_runtime.h>
#include <cuda_fp16.h>
#include <cstdint>

#define PP 2048
#define VV 32000
#define DD 100
#define NT1 256
#define NSEG 10
#define SEGV (VV / NSEG)          // 3200
#define TAILT (SEGV - 12 * NT1)   // 128

// ---- static device scratch (no dynamic allocation allowed) ----
__device__ __align__(16) __half g_wscr[(size_t)PP * VV];   // exp(z - mz_seg), fp16
__device__ __align__(16) __half g_WhT[(size_t)DD * VV];    // W transposed, fp16
__device__ float g_sm1[PP * NSEG];
__device__ float g_se1[PP * NSEG];
__device__ float g_sa1[PP * NSEG];
__device__ float g_smz[PP * NSEG];
__device__ float g_se2[PP * NSEG];
__device__ int   g_sai[PP * NSEG];
__device__ float g_scale[PP * NSEG];   // exp(mz_seg - MZ)/Z2, or 0 if row inactive
__device__ float g_ent[PP];

// -log(u + 1e-20), accurate near u==1 (where __logf's absolute error would
// corrupt the gumbel tail / argmax). Series uses exact d = 1-u for u >= 0.75.
__device__ __forceinline__ float neglog_u(float u) {
    float ue = u + 1e-20f;
    float d = 1.0f - ue;
    float s = d * (1.0f + d * (0.5f + d * (0.33333333f + d * (0.25f + d * (0.2f
             + d * (0.16666667f + d * (0.14285714f + d * (0.125f
             + d * 0.11111111f))))))));
    float l = -__logf(ue);
    return (ue >= 0.75f) ? s : l;
}
__device__ __forceinline__ float gumbel_g(float u) {
    return -__logf(neglog_u(u) + 1e-20f);
}

// ======== kernel 0: transpose W [V,D] f32 -> g_WhT [D,V] f16 ========
#define TK 64
__global__ void k_wconv(const float* __restrict__ W) {
    __shared__ float s[TK][DD + 1];
    const int k0 = blockIdx.x * TK;
    const int tid = threadIdx.x;
    for (int idx = tid; idx < TK * DD; idx += 256) {
        int r = idx / DD, d = idx - r * DD;
        s[r][d] = W[(size_t)(k0 + r) * DD + d];
    }
    __syncthreads();
    for (int idx = tid; idx < TK * DD; idx += 256) {
        int d = idx >> 6, r = idx & 63;
        g_WhT[(size_t)d * VV + k0 + r] = __float2half(s[r][d]);
    }
}

// ======== kernel 1: per-(row,segment) stats, single memory pass ========
__global__ void k_stats(const float* __restrict__ logits,
                        const float* __restrict__ gumb,
                        const int* __restrict__ obf_mask)
{
    const int pos = blockIdx.x;
    if (!obf_mask[pos]) return;
    const int seg = blockIdx.y;
    const int tid = threadIdx.x;
    const int base = seg * SEGV;
    const float* xr = logits + (size_t)pos * VV + base;
    const float* ur = gumb   + (size_t)pos * VV + base;

    float x[13], z[13];
    float m1 = -3.0e38f, mz = -3.0e38f;
    int ai = 0;
    #pragma unroll
    for (int j = 0; j < 13; j++) {
        const int i = tid + j * NT1;
        const bool v = (j < 12) || (tid < TAILT);
        if (v) {
            float xx = xr[i];
            float zz = xx + gumbel_g(ur[i]);
            x[j] = xx; z[j] = zz;
            m1 = fmaxf(m1, xx);
            if (zz > mz) { mz = zz; ai = base + i; }
        } else { x[j] = -3.0e38f; z[j] = -3.0e38f; }
    }
    const unsigned FULL = 0xffffffffu;
    #pragma unroll
    for (int off = 16; off; off >>= 1) {
        m1 = fmaxf(m1, __shfl_down_sync(FULL, m1, off));
        float oz = __shfl_down_sync(FULL, mz, off);
        int   oi = __shfl_down_sync(FULL, ai, off);
        if (oz > mz || (oz == mz && oi < ai)) { mz = oz; ai = oi; }
    }
    __shared__ float sA[8], sB[8];
    __shared__ int   sI[8];
    const int wid = tid >> 5, lane = tid & 31;
    if (lane == 0) { sA[wid] = m1; sB[wid] = mz; sI[wid] = ai; }
    __syncthreads();
    if (tid == 0) {
        #pragma unroll
        for (int w = 1; w < 8; w++) {
            m1 = fmaxf(m1, sA[w]);
            if (sB[w] > mz || (sB[w] == mz && sI[w] < ai)) { mz = sB[w]; ai = sI[w]; }
        }
        sA[0] = m1; sB[0] = mz; sI[0] = ai;
    }
    __syncthreads();
    const float M1 = sA[0], MZ = sB[0];
    const int   AI = sI[0];
    __syncthreads();

    float e1 = 0.f, a1 = 0.f, e2 = 0.f;
    __half* wr = g_wscr + (size_t)pos * VV + base;
    #pragma unroll
    for (int j = 0; j < 13; j++) {
        const int i = tid + j * NT1;
        const bool v = (j < 12) || (tid < TAILT);
        if (v) {
            float t = x[j] - M1;
            float p = __expf(t);
            e1 += p; a1 += p * t;
            float w = __expf(z[j] - MZ);
            e2 += w;
            wr[i] = __float2half(w);
        }
    }
    #pragma unroll
    for (int off = 16; off; off >>= 1) {
        e1 += __shfl_down_sync(FULL, e1, off);
        a1 += __shfl_down_sync(FULL, a1, off);
        e2 += __shfl_down_sync(FULL, e2, off);
    }
    __shared__ float sE1[8], sA1[8], sE2[8];
    if (lane == 0) { sE1[wid] = e1; sA1[wid] = a1; sE2[wid] = e2; }
    __syncthreads();
    if (tid == 0) {
        float E1 = 0.f, A1 = 0.f, E2 = 0.f;
        #pragma unroll
        for (int w = 0; w < 8; w++) { E1 += sE1[w]; A1 += sA1[w]; E2 += sE2[w]; }
        const int idx = pos * NSEG + seg;
        g_sm1[idx] = M1; g_se1[idx] = E1; g_sa1[idx] = A1;
        g_smz[idx] = MZ; g_se2[idx] = E2; g_sai[idx] = AI;
    }
}

// ======== kernel 2: per-row combine (1 warp/row) ========
__global__ void k_comb(const int* __restrict__ inp_word,
                       const int* __restrict__ obf_mask,
                       const float* __restrict__ W,
                       float* __restrict__ out)
{
    const int row = blockIdx.x * 8 + (threadIdx.x >> 5);
    const int lane = threadIdx.x & 31;
    const unsigned FULL = 0xffffffffu;
    float* out_word = out;
    float* out_emb  = out + PP;
    const int iw = inp_word[row];
    const int mk = obf_mask[row];

    if (!mk) {
        if (lane == 0) { out_word[row] = (float)iw; g_ent[row] = 0.0f; }
        if (lane < NSEG) g_scale[row * NSEG + lane] = 0.0f;
        for (int d = lane; d < DD; d += 32)
            out_emb[(size_t)row * DD + d] = W[(size_t)iw * DD + d];
        return;
    }

    const bool v = lane < NSEG;
    const int idx = row * NSEG + lane;
    float m1 = v ? g_sm1[idx] : -3.0e38f;
    float mz = v ? g_smz[idx] : -3.0e38f;
    int   ai = v ? g_sai[idx] : 0x7fffffff;
    float e1 = v ? g_se1[idx] : 0.f;
    float a1 = v ? g_sa1[idx] : 0.f;
    float e2 = v ? g_se2[idx] : 0.f;

    float M1 = m1, MZ = mz; int AI = ai;
    #pragma unroll
    for (int off = 16; off; off >>= 1) {
        M1 = fmaxf(M1, __shfl_xor_sync(FULL, M1, off));
        float omz = __shfl_xor_sync(FULL, MZ, off);
        int   oai = __shfl_xor_sync(FULL, AI, off);
        if (omz > MZ || (omz == MZ && oai < AI)) { MZ = omz; AI = oai; }
    }
    float E1 = v ? e1 * expf(m1 - M1) : 0.f;
    float A1 = v ? (a1 + (m1 - M1) * e1) * expf(m1 - M1) : 0.f;
    float E2 = v ? e2 * expf(mz - MZ) : 0.f;
    #pragma unroll
    for (int off = 16; off; off >>= 1) {
        E1 += __shfl_xor_sync(FULL, E1, off);
        A1 += __shfl_xor_sync(FULL, A1, off);
        E2 += __shfl_xor_sync(FULL, E2, off);
    }
    const int safe = (AI != iw) ? 1 : 0;
    if (lane == 0) {
        g_ent[row] = A1 / E1 - logf(E1);
        out_word[row] = safe ? (float)AI : 0.0f;   // UNK_ID = 0
    }
    if (v) g_scale[idx] = safe ? (expf(mz - MZ) / E2) : 0.0f;
    for (int d = lane; d < DD; d += 32)
        out_emb[(size_t)row * DD + d] = safe ? 0.0f : W[d];
}

// ======== kernel 3: fp16 tensor-core GEMM, k-split + atomic epilogue ========
#define MT 64
#define GKT 64
#define GNSPLIT 20
#define GKSEG (VV / GNSPLIT)   // 1600

__device__ __forceinline__ uint32_t s2u(const void* p) {
    return (uint32_t)__cvta_generic_to_shared(p);
}
__device__ __forceinline__ void ldsm4(uint32_t* r, uint32_t a) {
    asm volatile("ldmatrix.sync.aligned.m8n8.x4.shared.b16 {%0,%1,%2,%3},[%4];"
        : "=r"(r[0]), "=r"(r[1]), "=r"(r[2]), "=r"(r[3]) : "r"(a));
}
__device__ __forceinline__ void mma16816(float* c, const uint32_t* a,
                                         uint32_t b0, uint32_t b1) {
    asm volatile("mma.sync.aligned.m16n8k16.row.col.f32.f16.f16.f32 "
        "{%0,%1,%2,%3},{%4,%5,%6,%7},{%8,%9},{%0,%1,%2,%3};"
        : "+f"(c[0]), "+f"(c[1]), "+f"(c[2]), "+f"(c[3])
        : "r"(a[0]), "r"(a[1]), "r"(a[2]), "r"(a[3]), "r"(b0), "r"(b1));
}

#define ASTR 72   // halves per A row (36 half2, conflict-free)
#define BSTR 72   // halves per B row

__global__ void __launch_bounds__(128) k_gemm(float* __restrict__ out)
{
    float* out_emb = out + PP;
    const int rowBase = blockIdx.x * MT;
    const int kBase   = blockIdx.y * GKSEG;
    const int tid  = threadIdx.x;
    const int wid  = tid >> 5, lane = tid & 31;
    const int grp  = lane >> 2, tig = lane & 3;

    __shared__ __align__(16) __half As[MT * ASTR];
    __shared__ __align__(16) __half Bs[104 * BSTR];

    // zero the n=100..103 pad rows once (never rewritten)
    for (int i = tid; i < 4 * (BSTR / 2); i += 128)
        ((uint32_t*)Bs)[(100 + i / (BSTR / 2)) * (BSTR / 2) + i % (BSTR / 2)] = 0u;

    float c[13][4];
    #pragma unroll
    for (int j = 0; j < 13; j++) { c[j][0]=0.f; c[j][1]=0.f; c[j][2]=0.f; c[j][3]=0.f; }

    for (int kc = 0; kc < GKSEG; kc += GKT) {
        __syncthreads();
        // B: WhT rows 0..99, 64 halves each (coalesced 16B)
        const __half* bp = g_WhT + kBase + kc;
        #pragma unroll
        for (int it = 0; it < 7; it++) {
            int idx = tid + it * 128;
            if (idx < 800) {
                int n = idx >> 3, g = idx & 7;
                *(uint4*)(Bs + n * BSTR + g * 8) =
                    *(const uint4*)(bp + (size_t)n * VV + g * 8);
            }
        }
        // A: weight scratch, 64 rows x 64 halves
        const __half* ap = g_wscr + (size_t)rowBase * VV + kBase + kc;
        #pragma unroll
        for (int it = 0; it < 4; it++) {
            int idx = tid + it * 128;
            int r = idx >> 3, g = idx & 7;
            *(uint4*)(As + r * ASTR + g * 8) =
                *(const uint4*)(ap + (size_t)r * VV + g * 8);
        }
        __syncthreads();

        const int wrow = wid * 16;
        #pragma unroll
        for (int kh = 0; kh < 2; kh++) {
            const int ar = wrow + (lane & 7) + (lane & 8);
            const int ac = kh * 32 + ((lane >> 4) << 3);
            uint32_t a0[4], a1[4];
            ldsm4(a0, s2u(As + ar * ASTR + ac));
            ldsm4(a1, s2u(As + ar * ASTR + ac + 16));
            const int bc = kh * 32 + ((lane >> 3) << 3);
            #pragma unroll
            for (int j = 0; j < 13; j++) {
                uint32_t b[4];
                ldsm4(b, s2u(Bs + (j * 8 + (lane & 7)) * BSTR + bc));
                mma16816(c[j], a0, b[0], b[1]);
                mma16816(c[j], a1, b[2], b[3]);
            }
        }
    }

    // epilogue: scale by per-(row,seg) factor, atomic accumulate
    const int sseg = blockIdx.y >> 1;     // GKSEG(1600) pairs -> stats seg(3200)
    const int r0 = rowBase + wid * 16 + grp;
    const int r1 = r0 + 8;
    const float s0 = g_scale[r0 * NSEG + sseg];
    const float s1 = g_scale[r1 * NSEG + sseg];
    #pragma unroll
    for (int j = 0; j < 13; j++) {
        int col = j * 8 + tig * 2;
        if (col < DD) {
            if (s0 != 0.f) atomicAdd(&out_emb[(size_t)r0 * DD + col], c[j][0] * s0);
            if (s1 != 0.f) atomicAdd(&out_emb[(size_t)r1 * DD + col], c[j][2] * s1);
        }
        if (col + 1 < DD) {
            if (s0 != 0.f) atomicAdd(&out_emb[(size_t)r0 * DD + col + 1], c[j][1] * s0);
            if (s1 != 0.f) atomicAdd(&out_emb[(size_t)r1 * DD + col + 1], c[j][3] * s1);
        }
    }
}

// ======== kernel 4: entropy loss reduction ========
__global__ void k_ent(const int* __restrict__ obf_mask, float* __restrict__ out)
{
    __shared__ float ss[256];
    __shared__ int   sc[256];
    const int tid = threadIdx.x;
    float s = 0.f; int c = 0;
    for (int i = tid; i < PP; i += 256) { s += g_ent[i]; c += obf_mask[i]; }
    ss[tid] = s; sc[tid] = c;
    __syncthreads();
    for (int o = 128; o; o >>= 1) {
        if (tid < o) { ss[tid] += ss[tid + o]; sc[tid] += sc[tid + o]; }
        __syncthreads();
    }
    if (tid == 0) {
        float n = (float)sc[0];
        out[PP + (size_t)PP * DD] = ss[0] / (n * (float)VV);
    }
}

// ======== launch ========
extern "C" void kernel_launch(void* const* d_in, const int* in_sizes, int n_in,
                              void* d_out, int out_size)
{
    (void)in_sizes; (void)n_in; (void)out_size;
    const float* logits = (const float*)d_in[0];
    const float* gumb   = (const float*)d_in[1];
    const int*   inp    = (const int*)d_in[2];
    const int*   mask   = (const int*)d_in[3];
    const float* W      = (const float*)d_in[4];
    float* out = (float*)d_out;

    k_wconv<<<VV / TK, 256>>>(W);
    dim3 gs(PP, NSEG);
    k_stats<<<gs, NT1>>>(logits, gumb, mask);
    k_comb<<<PP / 8, 256>>>(inp, mask, W, out);
    dim3 gg(PP / MT, GNSPLIT);
    k_gemm<<<gg, 128>>>(out);
    k_ent<<<1, 256>>>(mask, out);
}

// round 6
// speedup vs baseline: 2.0211x; 1.3823x over previous
#include <cuda_runtime.h>
#include <cuda_fp16.h>
#include <cstdint>

#define PP 2048
#define VV 32000
#define DD 100
#define NT1 256
#define NSEG 10
#define SEGV (VV / NSEG)          // 3200
#define SEGV4 (SEGV / 4)          // 800 float4

// ---- static device scratch (no dynamic allocation allowed) ----
__device__ __align__(16) __half g_wscr[(size_t)PP * VV];   // exp(z - mz_seg), fp16
__device__ __align__(16) __half g_WhT[(size_t)DD * VV];    // W transposed, fp16
__device__ float g_sm1[PP * NSEG];
__device__ float g_se1[PP * NSEG];
__device__ float g_sa1[PP * NSEG];
__device__ float g_smz[PP * NSEG];
__device__ float g_se2[PP * NSEG];
__device__ int   g_sai[PP * NSEG];
__device__ float g_scale[PP * NSEG];   // exp(mz_seg - MZ)/Z2, or 0 if row inactive
__device__ float g_ent[PP];

// -log(u + 1e-20), accurate near u==1 (where __logf's absolute error would
// corrupt the gumbel tail / argmax). Series uses exact d = 1-u for u >= 0.75.
__device__ __forceinline__ float neglog_u(float u) {
    float ue = u + 1e-20f;
    float d = 1.0f - ue;
    float s = d * (1.0f + d * (0.5f + d * (0.33333333f + d * (0.25f + d * (0.2f
             + d * (0.16666667f + d * (0.14285714f + d * (0.125f
             + d * 0.11111111f))))))));
    float l = -__logf(ue);
    return (ue >= 0.75f) ? s : l;
}
__device__ __forceinline__ float gumbel_g(float u) {
    return -__logf(neglog_u(u) + 1e-20f);
}

// ======== kernel 0: transpose W [V,D] f32 -> g_WhT [D,V] f16 ========
#define TK 64
__global__ void k_wconv(const float* __restrict__ W) {
    __shared__ float s[TK][DD + 1];
    const int k0 = blockIdx.x * TK;
    const int tid = threadIdx.x;
    for (int idx = tid; idx < TK * DD; idx += 256) {
        int r = idx / DD, d = idx - r * DD;
        s[r][d] = W[(size_t)(k0 + r) * DD + d];
    }
    __syncthreads();
    for (int idx = tid; idx < TK * DD; idx += 256) {
        int d = idx >> 6, r = idx & 63;
        g_WhT[(size_t)d * VV + k0 + r] = __float2half(s[r][d]);
    }
}

// ======== kernel 1: per-(row,segment) stats, single memory pass, float4 ========
__global__ void k_stats(const float* __restrict__ logits,
                        const float* __restrict__ gumb,
                        const int* __restrict__ obf_mask)
{
    const int pos = blockIdx.x;
    if (!obf_mask[pos]) return;
    const int seg = blockIdx.y;
    const int tid = threadIdx.x;
    const int base = seg * SEGV;
    const float4* x4 = (const float4*)(logits + (size_t)pos * VV + base);
    const float4* u4 = (const float4*)(gumb   + (size_t)pos * VV + base);

    float x[16], z[16];
    float m1 = -3.0e38f, mz = -3.0e38f;
    int ai = 0;
    // j=0..2 full (768 float4), j=3 tail (32 float4, tid<32)
    #pragma unroll
    for (int j = 0; j < 4; j++) {
        const int idx = (j < 3) ? (tid + j * NT1) : (768 + tid);
        const bool v = (j < 3) || (tid < 32);
        if (v) {
            float4 xx = x4[idx];
            float4 uu = u4[idx];
            const float* xe = &xx.x;
            const float* ue = &uu.x;
            #pragma unroll
            for (int e = 0; e < 4; e++) {
                float xv = xe[e];
                float zv = xv + gumbel_g(ue[e]);
                x[j*4+e] = xv; z[j*4+e] = zv;
                m1 = fmaxf(m1, xv);
                if (zv > mz) { mz = zv; ai = base + idx * 4 + e; }
            }
        } else {
            #pragma unroll
            for (int e = 0; e < 4; e++) { x[j*4+e] = -3.0e38f; z[j*4+e] = -3.0e38f; }
        }
    }
    const unsigned FULL = 0xffffffffu;
    #pragma unroll
    for (int off = 16; off; off >>= 1) {
        m1 = fmaxf(m1, __shfl_down_sync(FULL, m1, off));
        float oz = __shfl_down_sync(FULL, mz, off);
        int   oi = __shfl_down_sync(FULL, ai, off);
        if (oz > mz || (oz == mz && oi < ai)) { mz = oz; ai = oi; }
    }
    __shared__ float sA[8], sB[8];
    __shared__ int   sI[8];
    const int wid = tid >> 5, lane = tid & 31;
    if (lane == 0) { sA[wid] = m1; sB[wid] = mz; sI[wid] = ai; }
    __syncthreads();
    if (tid == 0) {
        #pragma unroll
        for (int w = 1; w < 8; w++) {
            m1 = fmaxf(m1, sA[w]);
            if (sB[w] > mz || (sB[w] == mz && sI[w] < ai)) { mz = sB[w]; ai = sI[w]; }
        }
        sA[0] = m1; sB[0] = mz; sI[0] = ai;
    }
    __syncthreads();
    const float M1 = sA[0], MZ = sB[0];
    const int   AI = sI[0];
    __syncthreads();

    float e1 = 0.f, a1 = 0.f, e2 = 0.f;
    __half* wr = g_wscr + (size_t)pos * VV + base;
    #pragma unroll
    for (int j = 0; j < 4; j++) {
        const int idx = (j < 3) ? (tid + j * NT1) : (768 + tid);
        const bool v = (j < 3) || (tid < 32);
        if (v) {
            float w0, w1, w2, w3;
            #pragma unroll
            for (int e = 0; e < 4; e++) {
                float t = x[j*4+e] - M1;
                float p = __expf(t);
                e1 += p; a1 += p * t;
            }
            w0 = __expf(z[j*4+0] - MZ);
            w1 = __expf(z[j*4+1] - MZ);
            w2 = __expf(z[j*4+2] - MZ);
            w3 = __expf(z[j*4+3] - MZ);
            e2 += (w0 + w1) + (w2 + w3);
            __half2 h0 = __floats2half2_rn(w0, w1);
            __half2 h1 = __floats2half2_rn(w2, w3);
            uint2 pk;
            pk.x = *(uint32_t*)&h0;
            pk.y = *(uint32_t*)&h1;
            *(uint2*)(wr + idx * 4) = pk;
        }
    }
    #pragma unroll
    for (int off = 16; off; off >>= 1) {
        e1 += __shfl_down_sync(FULL, e1, off);
        a1 += __shfl_down_sync(FULL, a1, off);
        e2 += __shfl_down_sync(FULL, e2, off);
    }
    __shared__ float sE1[8], sA1[8], sE2[8];
    if (lane == 0) { sE1[wid] = e1; sA1[wid] = a1; sE2[wid] = e2; }
    __syncthreads();
    if (tid == 0) {
        float E1 = 0.f, A1 = 0.f, E2 = 0.f;
        #pragma unroll
        for (int w = 0; w < 8; w++) { E1 += sE1[w]; A1 += sA1[w]; E2 += sE2[w]; }
        const int idx = pos * NSEG + seg;
        g_sm1[idx] = M1; g_se1[idx] = E1; g_sa1[idx] = A1;
        g_smz[idx] = MZ; g_se2[idx] = E2; g_sai[idx] = AI;
    }
}

// ======== kernel 2: per-row combine (1 warp/row) ========
__global__ void k_comb(const int* __restrict__ inp_word,
                       const int* __restrict__ obf_mask,
                       const float* __restrict__ W,
                       float* __restrict__ out)
{
    const int row = blockIdx.x * 8 + (threadIdx.x >> 5);
    const int lane = threadIdx.x & 31;
    const unsigned FULL = 0xffffffffu;
    float* out_word = out;
    float* out_emb  = out + PP;
    const int iw = inp_word[row];
    const int mk = obf_mask[row];

    if (!mk) {
        if (lane == 0) { out_word[row] = (float)iw; g_ent[row] = 0.0f; }
        if (lane < NSEG) g_scale[row * NSEG + lane] = 0.0f;
        for (int d = lane; d < DD; d += 32)
            out_emb[(size_t)row * DD + d] = W[(size_t)iw * DD + d];
        return;
    }

    const bool v = lane < NSEG;
    const int idx = row * NSEG + lane;
    float m1 = v ? g_sm1[idx] : -3.0e38f;
    float mz = v ? g_smz[idx] : -3.0e38f;
    int   ai = v ? g_sai[idx] : 0x7fffffff;
    float e1 = v ? g_se1[idx] : 0.f;
    float a1 = v ? g_sa1[idx] : 0.f;
    float e2 = v ? g_se2[idx] : 0.f;

    float M1 = m1, MZ = mz; int AI = ai;
    #pragma unroll
    for (int off = 16; off; off >>= 1) {
        M1 = fmaxf(M1, __shfl_xor_sync(FULL, M1, off));
        float omz = __shfl_xor_sync(FULL, MZ, off);
        int   oai = __shfl_xor_sync(FULL, AI, off);
        if (omz > MZ || (omz == MZ && oai < AI)) { MZ = omz; AI = oai; }
    }
    float E1 = v ? e1 * expf(m1 - M1) : 0.f;
    float A1 = v ? (a1 + (m1 - M1) * e1) * expf(m1 - M1) : 0.f;
    float E2 = v ? e2 * expf(mz - MZ) : 0.f;
    #pragma unroll
    for (int off = 16; off; off >>= 1) {
        E1 += __shfl_xor_sync(FULL, E1, off);
        A1 += __shfl_xor_sync(FULL, A1, off);
        E2 += __shfl_xor_sync(FULL, E2, off);
    }
    const int safe = (AI != iw) ? 1 : 0;
    if (lane == 0) {
        g_ent[row] = A1 / E1 - logf(E1);
        out_word[row] = safe ? (float)AI : 0.0f;   // UNK_ID = 0
    }
    if (v) g_scale[idx] = safe ? (expf(mz - MZ) / E2) : 0.0f;
    for (int d = lane; d < DD; d += 32)
        out_emb[(size_t)row * DD + d] = safe ? 0.0f : W[d];
}

// ======== kernel 3: fp16 tensor-core GEMM, cp.async pipeline ========
#define MT 64
#define GKT 64
#define GNSPLIT 20
#define GKSEG (VV / GNSPLIT)   // 1600

__device__ __forceinline__ uint32_t s2u(const void* p) {
    return (uint32_t)__cvta_generic_to_shared(p);
}
__device__ __forceinline__ void ldsm4(uint32_t* r, uint32_t a) {
    asm volatile("ldmatrix.sync.aligned.m8n8.x4.shared.b16 {%0,%1,%2,%3},[%4];"
        : "=r"(r[0]), "=r"(r[1]), "=r"(r[2]), "=r"(r[3]) : "r"(a));
}
__device__ __forceinline__ void mma16816(float* c, const uint32_t* a,
                                         uint32_t b0, uint32_t b1) {
    asm volatile("mma.sync.aligned.m16n8k16.row.col.f32.f16.f16.f32 "
        "{%0,%1,%2,%3},{%4,%5,%6,%7},{%8,%9},{%0,%1,%2,%3};"
        : "+f"(c[0]), "+f"(c[1]), "+f"(c[2]), "+f"(c[3])
        : "r"(a[0]), "r"(a[1]), "r"(a[2]), "r"(a[3]), "r"(b0), "r"(b1));
}
__device__ __forceinline__ void cpa16(uint32_t s, const void* g) {
    asm volatile("cp.async.cg.shared.global [%0], [%1], 16;" :: "r"(s), "l"(g));
}
#define CP_COMMIT() asm volatile("cp.async.commit_group;")
#define CP_WAIT1()  asm volatile("cp.async.wait_group 1;")

#define ASTR 72   // halves per A row (conflict-free ldmatrix: 144B stride)
#define BSTR 72

__global__ void __launch_bounds__(128) k_gemm(float* __restrict__ out)
{
    float* out_emb = out + PP;
    const int rowBase = blockIdx.x * MT;
    const int kBase   = blockIdx.y * GKSEG;
    const int tid  = threadIdx.x;
    const int wid  = tid >> 5, lane = tid & 31;
    const int grp  = lane >> 2, tig = lane & 3;

    __shared__ __align__(16) __half As[2][MT * ASTR];
    __shared__ __align__(16) __half Bs[2][104 * BSTR];

    // zero pad rows n=100..103 (both stages; never rewritten)
    for (int i = tid; i < 2 * 4 * (BSTR / 2); i += 128) {
        int s = i / (4 * (BSTR / 2));
        int rem = i % (4 * (BSTR / 2));
        int r = rem / (BSTR / 2), c = rem % (BSTR / 2);
        ((uint32_t*)Bs[s])[(100 + r) * (BSTR / 2) + c] = 0u;
    }

    float c[13][4];
    #pragma unroll
    for (int j = 0; j < 13; j++) { c[j][0]=0.f; c[j][1]=0.f; c[j][2]=0.f; c[j][3]=0.f; }

    const __half* aG = g_wscr + (size_t)rowBase * VV + kBase;
    const __half* bG = g_WhT + kBase;

    auto load_stage = [&](int s, int kc) {
        #pragma unroll
        for (int it = 0; it < 7; it++) {
            int idx = tid + it * 128;
            if (idx < 800) {
                int n = idx >> 3, g = idx & 7;
                cpa16(s2u(&Bs[s][n * BSTR + g * 8]), bG + (size_t)n * VV + kc + g * 8);
            }
        }
        #pragma unroll
        for (int it = 0; it < 4; it++) {
            int idx = tid + it * 128;
            int r = idx >> 3, g = idx & 7;
            cpa16(s2u(&As[s][r * ASTR + g * 8]), aG + (size_t)r * VV + kc + g * 8);
        }
        CP_COMMIT();
    };

    load_stage(0, 0);
    int s = 0;
    for (int kc = 0; kc < GKSEG; kc += GKT, s ^= 1) {
        if (kc + GKT < GKSEG) load_stage(s ^ 1, kc + GKT);
        else CP_COMMIT();
        CP_WAIT1();
        __syncthreads();

        const int wrow = wid * 16;
        #pragma unroll
        for (int kh = 0; kh < 2; kh++) {
            const int ar = wrow + (lane & 7) + (lane & 8);
            const int ac = kh * 32 + ((lane >> 4) << 3);
            uint32_t a0[4], a1[4];
            ldsm4(a0, s2u(&As[s][ar * ASTR + ac]));
            ldsm4(a1, s2u(&As[s][ar * ASTR + ac + 16]));
            const int bc = kh * 32 + ((lane >> 3) << 3);
            #pragma unroll
            for (int j = 0; j < 13; j++) {
                uint32_t b[4];
                ldsm4(b, s2u(&Bs[s][(j * 8 + (lane & 7)) * BSTR + bc]));
                mma16816(c[j], a0, b[0], b[1]);
                mma16816(c[j], a1, b[2], b[3]);
            }
        }
        __syncthreads();
    }

    // epilogue: scale by per-(row,seg) factor, atomic accumulate
    const int sseg = blockIdx.y >> 1;     // GKSEG(1600) pairs -> stats seg(3200)
    const int r0 = rowBase + wid * 16 + grp;
    const int r1 = r0 + 8;
    const float s0 = g_scale[r0 * NSEG + sseg];
    const float s1 = g_scale[r1 * NSEG + sseg];
    #pragma unroll
    for (int j = 0; j < 13; j++) {
        int col = j * 8 + tig * 2;
        if (col < DD) {
            if (s0 != 0.f) atomicAdd(&out_emb[(size_t)r0 * DD + col], c[j][0] * s0);
            if (s1 != 0.f) atomicAdd(&out_emb[(size_t)r1 * DD + col], c[j][2] * s1);
        }
        if (col + 1 < DD) {
            if (s0 != 0.f) atomicAdd(&out_emb[(size_t)r0 * DD + col + 1], c[j][1] * s0);
            if (s1 != 0.f) atomicAdd(&out_emb[(size_t)r1 * DD + col + 1], c[j][3] * s1);
        }
    }
}

// ======== kernel 4: entropy loss reduction ========
__global__ void k_ent(const int* __restrict__ obf_mask, float* __restrict__ out)
{
    __shared__ float ss[256];
    __shared__ int   sc[256];
    const int tid = threadIdx.x;
    float s = 0.f; int c = 0;
    for (int i = tid; i < PP; i += 256) { s += g_ent[i]; c += obf_mask[i]; }
    ss[tid] = s; sc[tid] = c;
    __syncthreads();
    for (int o = 128; o; o >>= 1) {
        if (tid < o) { ss[tid] += ss[tid + o]; sc[tid] += sc[tid + o]; }
        __syncthreads();
    }
    if (tid == 0) {
        float n = (float)sc[0];
        out[PP + (size_t)PP * DD] = ss[0] / (n * (float)VV);
    }
}

// ======== launch ========
extern "C" void kernel_launch(void* const* d_in, const int* in_sizes, int n_in,
                              void* d_out, int out_size)
{
    (void)in_sizes; (void)n_in; (void)out_size;
    const float* logits = (const float*)d_in[0];
    const float* gumb   = (const float*)d_in[1];
    const int*   inp    = (const int*)d_in[2];
    const int*   mask   = (const int*)d_in[3];
    const float* W      = (const float*)d_in[4];
    float* out = (float*)d_out;

    k_wconv<<<VV / TK, 256>>>(W);
    dim3 gs(PP, NSEG);
    k_stats<<<gs, NT1>>>(logits, gumb, mask);
    k_comb<<<PP / 8, 256>>>(inp, mask, W, out);
    dim3 gg(PP / MT, GNSPLIT);
    k_gemm<<<gg, 128>>>(out);
    k_ent<<<1, 256>>>(mask, out);
}

// round 7
// speedup vs baseline: 2.1107x; 1.0443x over previous
#include <cuda_runtime.h>
#include <cuda_fp16.h>
#include <cstdint>

#define PP 2048
#define VV 32000
#define DD 100
#define NT1 256
#define NSEG 10
#define SEGV (VV / NSEG)          // 3200

// ---- static device scratch (no dynamic allocation allowed) ----
__device__ __align__(16) __half g_wscr[(size_t)PP * VV];   // exp(z - mz_seg), fp16
__device__ __align__(16) __half g_WhT[(size_t)DD * VV];    // W transposed, fp16
__device__ float g_sm1[PP * NSEG];
__device__ float g_se1[PP * NSEG];
__device__ float g_sa1[PP * NSEG];
__device__ float g_smz[PP * NSEG];
__device__ float g_se2[PP * NSEG];
__device__ int   g_sai[PP * NSEG];
__device__ float g_scale[PP * NSEG];   // exp(mz_seg - MZ)/Z2, or 0 if row inactive
__device__ float g_ent[PP];
__device__ int   g_rows[PP];           // compacted masked-row indices
__device__ int   g_nmask;

// -log(u + 1e-20), accurate near u==1 (where __logf's absolute error would
// corrupt the gumbel tail / argmax). Series uses exact d = 1-u for u >= 0.75.
__device__ __forceinline__ float neglog_u(float u) {
    float ue = u + 1e-20f;
    float d = 1.0f - ue;
    float s = d * (1.0f + d * (0.5f + d * (0.33333333f + d * (0.25f + d * (0.2f
             + d * (0.16666667f + d * (0.14285714f + d * (0.125f
             + d * 0.11111111f))))))));
    float l = -__logf(ue);
    return (ue >= 0.75f) ? s : l;
}
__device__ __forceinline__ float gumbel_g(float u) {
    return -__logf(neglog_u(u) + 1e-20f);
}

// ======== kernel 0: transpose W [V,D] f32 -> g_WhT [D,V] f16 ========
#define TK 64
__global__ void k_wconv(const float* __restrict__ W) {
    __shared__ float s[TK][DD + 1];
    const int k0 = blockIdx.x * TK;
    const int tid = threadIdx.x;
    for (int idx = tid; idx < TK * DD; idx += 256) {
        int r = idx / DD, d = idx - r * DD;
        s[r][d] = W[(size_t)(k0 + r) * DD + d];
    }
    __syncthreads();
    for (int idx = tid; idx < TK * DD; idx += 256) {
        int d = idx >> 6, r = idx & 63;
        g_WhT[(size_t)d * VV + k0 + r] = __float2half(s[r][d]);
    }
}

// ======== kernel 0b: compact masked rows (deterministic scan) ========
__global__ void k_scan(const int* __restrict__ mask) {
    __shared__ int sp[1024];
    const int t = threadIdx.x;
    const int m0 = mask[2 * t], m1 = mask[2 * t + 1];
    const int loc = m0 + m1;
    sp[t] = loc;
    __syncthreads();
    for (int off = 1; off < 1024; off <<= 1) {
        int v = (t >= off) ? sp[t - off] : 0;
        __syncthreads();
        sp[t] += v;
        __syncthreads();
    }
    const int excl = sp[t] - loc;
    if (m0) g_rows[excl] = 2 * t;
    if (m1) g_rows[excl + m0] = 2 * t + 1;
    if (t == 1023) g_nmask = sp[t];
}

// ======== kernel 1: per-(row,segment) stats, single memory pass ========
// Each thread owns 16 elements as two 8-element contiguous chunks:
//   chunk A at float4 idx {2t, 2t+1}, chunk B at {512+2t, 513+2t} (t<144).
__global__ void k_stats(const float* __restrict__ logits,
                        const float* __restrict__ gumb,
                        const int* __restrict__ obf_mask)
{
    const int pos = blockIdx.x;
    if (!obf_mask[pos]) return;
    const int seg = blockIdx.y;
    const int tid = threadIdx.x;
    const int base = seg * SEGV;
    const float4* x4 = (const float4*)(logits + (size_t)pos * VV + base);
    const float4* u4 = (const float4*)(gumb   + (size_t)pos * VV + base);

    const int iA = 2 * tid;
    const int iB = 512 + 2 * tid;
    const bool vB = (tid < 144);

    // hoisted loads: up to 8 outstanding LDG.128
    float4 XV[4], UV[4];
    XV[0] = x4[iA];     XV[1] = x4[iA + 1];
    UV[0] = u4[iA];     UV[1] = u4[iA + 1];
    if (vB) {
        XV[2] = x4[iB]; XV[3] = x4[iB + 1];
        UV[2] = u4[iB]; UV[3] = u4[iB + 1];
    } else {
        XV[2] = make_float4(-3.0e38f, -3.0e38f, -3.0e38f, -3.0e38f);
        XV[3] = XV[2];
        UV[2] = make_float4(0.5f, 0.5f, 0.5f, 0.5f);
        UV[3] = UV[2];
    }

    float x[16], z[16];
    float m1 = -3.0e38f, mz = -3.0e38f;
    int ai = 0;
    #pragma unroll
    for (int j = 0; j < 4; j++) {
        const int e0 = base + ((j < 2) ? (iA + j) : (iB + j - 2)) * 4;
        const float* xe = &XV[j].x;
        const float* ue = &UV[j].x;
        #pragma unroll
        for (int e = 0; e < 4; e++) {
            float xv = xe[e];
            float zv = xv + gumbel_g(ue[e]);
            x[j*4+e] = xv; z[j*4+e] = zv;
            m1 = fmaxf(m1, xv);
            if (zv > mz) { mz = zv; ai = e0 + e; }
        }
    }
    const unsigned FULL = 0xffffffffu;
    #pragma unroll
    for (int off = 16; off; off >>= 1) {
        m1 = fmaxf(m1, __shfl_down_sync(FULL, m1, off));
        float oz = __shfl_down_sync(FULL, mz, off);
        int   oi = __shfl_down_sync(FULL, ai, off);
        if (oz > mz || (oz == mz && oi < ai)) { mz = oz; ai = oi; }
    }
    __shared__ float sA[8], sB[8];
    __shared__ int   sI[8];
    const int wid = tid >> 5, lane = tid & 31;
    if (lane == 0) { sA[wid] = m1; sB[wid] = mz; sI[wid] = ai; }
    __syncthreads();
    if (tid == 0) {
        #pragma unroll
        for (int w = 1; w < 8; w++) {
            m1 = fmaxf(m1, sA[w]);
            if (sB[w] > mz || (sB[w] == mz && sI[w] < ai)) { mz = sB[w]; ai = sI[w]; }
        }
        sA[0] = m1; sB[0] = mz; sI[0] = ai;
    }
    __syncthreads();
    const float M1 = sA[0], MZ = sB[0];
    const int   AI = sI[0];
    __syncthreads();

    float e1 = 0.f, a1 = 0.f, e2 = 0.f;
    __half* wr = g_wscr + (size_t)pos * VV + base;
    float w[16];
    #pragma unroll
    for (int j = 0; j < 4; j++) {
        #pragma unroll
        for (int e = 0; e < 4; e++) {
            const int q = j*4+e;
            float t = x[q] - M1;
            float p = __expf(t);
            e1 += p; a1 += p * t;
            float ww = __expf(z[q] - MZ);
            w[q] = ww;
        }
    }
    #pragma unroll
    for (int q = 0; q < 16; q++) e2 += (q < 8 || vB) ? w[q] : 0.f;
    {
        __half2 h0 = __floats2half2_rn(w[0], w[1]);
        __half2 h1 = __floats2half2_rn(w[2], w[3]);
        __half2 h2 = __floats2half2_rn(w[4], w[5]);
        __half2 h3 = __floats2half2_rn(w[6], w[7]);
        uint4 pk;
        pk.x = *(uint32_t*)&h0; pk.y = *(uint32_t*)&h1;
        pk.z = *(uint32_t*)&h2; pk.w = *(uint32_t*)&h3;
        *(uint4*)(wr + iA * 4) = pk;
    }
    if (vB) {
        __half2 h0 = __floats2half2_rn(w[8],  w[9]);
        __half2 h1 = __floats2half2_rn(w[10], w[11]);
        __half2 h2 = __floats2half2_rn(w[12], w[13]);
        __half2 h3 = __floats2half2_rn(w[14], w[15]);
        uint4 pk;
        pk.x = *(uint32_t*)&h0; pk.y = *(uint32_t*)&h1;
        pk.z = *(uint32_t*)&h2; pk.w = *(uint32_t*)&h3;
        *(uint4*)(wr + iB * 4) = pk;
    }
    // mask invalid-lane entropy contributions (x was -3e38 -> p==0, p*t==0*inf? guard)
    if (!vB) { /* x=-3e38: t=-inf, p=0, p*t = 0*-inf = nan! */ }
    #pragma unroll
    for (int off = 16; off; off >>= 1) {
        e1 += __shfl_down_sync(FULL, e1, off);
        a1 += __shfl_down_sync(FULL, a1, off);
        e2 += __shfl_down_sync(FULL, e2, off);
    }
    __shared__ float sE1[8], sA1[8], sE2[8];
    if (lane == 0) { sE1[wid] = e1; sA1[wid] = a1; sE2[wid] = e2; }
    __syncthreads();
    if (tid == 0) {
        float E1 = 0.f, A1 = 0.f, E2 = 0.f;
        #pragma unroll
        for (int w2 = 0; w2 < 8; w2++) { E1 += sE1[w2]; A1 += sA1[w2]; E2 += sE2[w2]; }
        const int idx = pos * NSEG + seg;
        g_sm1[idx] = M1; g_se1[idx] = E1; g_sa1[idx] = A1;
        g_smz[idx] = MZ; g_se2[idx] = E2; g_sai[idx] = AI;
    }
}

// ======== kernel 2: per-row combine (1 warp/row) ========
__global__ void k_comb(const int* __restrict__ inp_word,
                       const int* __restrict__ obf_mask,
                       const float* __restrict__ W,
                       float* __restrict__ out)
{
    const int row = blockIdx.x * 8 + (threadIdx.x >> 5);
    const int lane = threadIdx.x & 31;
    const unsigned FULL = 0xffffffffu;
    float* out_word = out;
    float* out_emb  = out + PP;
    const int iw = inp_word[row];
    const int mk = obf_mask[row];

    if (!mk) {
        if (lane == 0) { out_word[row] = (float)iw; g_ent[row] = 0.0f; }
        if (lane < NSEG) g_scale[row * NSEG + lane] = 0.0f;
        for (int d = lane; d < DD; d += 32)
            out_emb[(size_t)row * DD + d] = W[(size_t)iw * DD + d];
        return;
    }

    const bool v = lane < NSEG;
    const int idx = row * NSEG + lane;
    float m1 = v ? g_sm1[idx] : -3.0e38f;
    float mz = v ? g_smz[idx] : -3.0e38f;
    int   ai = v ? g_sai[idx] : 0x7fffffff;
    float e1 = v ? g_se1[idx] : 0.f;
    float a1 = v ? g_sa1[idx] : 0.f;
    float e2 = v ? g_se2[idx] : 0.f;

    float M1 = m1, MZ = mz; int AI = ai;
    #pragma unroll
    for (int off = 16; off; off >>= 1) {
        M1 = fmaxf(M1, __shfl_xor_sync(FULL, M1, off));
        float omz = __shfl_xor_sync(FULL, MZ, off);
        int   oai = __shfl_xor_sync(FULL, AI, off);
        if (omz > MZ || (omz == MZ && oai < AI)) { MZ = omz; AI = oai; }
    }
    float E1 = v ? e1 * expf(m1 - M1) : 0.f;
    float A1 = v ? (a1 + (m1 - M1) * e1) * expf(m1 - M1) : 0.f;
    float E2 = v ? e2 * expf(mz - MZ) : 0.f;
    #pragma unroll
    for (int off = 16; off; off >>= 1) {
        E1 += __shfl_xor_sync(FULL, E1, off);
        A1 += __shfl_xor_sync(FULL, A1, off);
        E2 += __shfl_xor_sync(FULL, E2, off);
    }
    const int safe = (AI != iw) ? 1 : 0;
    if (lane == 0) {
        g_ent[row] = A1 / E1 - logf(E1);
        out_word[row] = safe ? (float)AI : 0.0f;   // UNK_ID = 0
    }
    if (v) g_scale[idx] = safe ? (expf(mz - MZ) / E2) : 0.0f;
    for (int d = lane; d < DD; d += 32)
        out_emb[(size_t)row * DD + d] = safe ? 0.0f : W[d];
}

// ======== kernel 3: fp16 tensor-core GEMM on compacted rows ========
#define MT 128
#define GKT 64
#define GNSPLIT 50
#define GKSEG (VV / GNSPLIT)   // 640
#define GTHR 256

__device__ __forceinline__ uint32_t s2u(const void* p) {
    return (uint32_t)__cvta_generic_to_shared(p);
}
__device__ __forceinline__ void ldsm4(uint32_t* r, uint32_t a) {
    asm volatile("ldmatrix.sync.aligned.m8n8.x4.shared.b16 {%0,%1,%2,%3},[%4];"
        : "=r"(r[0]), "=r"(r[1]), "=r"(r[2]), "=r"(r[3]) : "r"(a));
}
__device__ __forceinline__ void mma16816(float* c, const uint32_t* a,
                                         uint32_t b0, uint32_t b1) {
    asm volatile("mma.sync.aligned.m16n8k16.row.col.f32.f16.f16.f32 "
        "{%0,%1,%2,%3},{%4,%5,%6,%7},{%8,%9},{%0,%1,%2,%3};"
        : "+f"(c[0]), "+f"(c[1]), "+f"(c[2]), "+f"(c[3])
        : "r"(a[0]), "r"(a[1]), "r"(a[2]), "r"(a[3]), "r"(b0), "r"(b1));
}
__device__ __forceinline__ void cpa16(uint32_t s, const void* g) {
    asm volatile("cp.async.cg.shared.global [%0], [%1], 16;" :: "r"(s), "l"(g));
}
#define CP_COMMIT() asm volatile("cp.async.commit_group;")
#define CP_WAIT1()  asm volatile("cp.async.wait_group 1;")

#define ASTR 72
#define BSTR 72
#define GSMEM (2*MT*ASTR*2 + 2*104*BSTR*2 + MT*4)   // 67328 bytes

__global__ void __launch_bounds__(GTHR) k_gemm(float* __restrict__ out)
{
    const int nm = g_nmask;
    const int rowBase = blockIdx.x * MT;
    if (rowBase >= nm) return;

    extern __shared__ __align__(16) char dyn[];
    __half* As = (__half*)dyn;                       // [2][MT][ASTR]
    __half* Bs = As + 2 * MT * ASTR;                 // [2][104][BSTR]
    int*  sRow = (int*)(Bs + 2 * 104 * BSTR);        // [MT]

    float* out_emb = out + PP;
    const int kBase = blockIdx.y * GKSEG;
    const int tid = threadIdx.x;
    const int wid = tid >> 5, lane = tid & 31;
    const int grp = lane >> 2, tig = lane & 3;

    for (int i = tid; i < MT; i += GTHR) {
        int slot = rowBase + i;
        sRow[i] = g_rows[(slot < nm) ? slot : 0];
    }
    // zero B pad rows 100..103, both stages (36 u32 per row)
    for (int i = tid; i < 288; i += GTHR) {
        int st = i / 144, rem = i % 144;
        int r = rem / 36, c2 = rem % 36;
        ((uint32_t*)(Bs + st * 104 * BSTR + (100 + r) * BSTR))[c2] = 0u;
    }
    __syncthreads();

    float c[13][4];
    #pragma unroll
    for (int j = 0; j < 13; j++) { c[j][0]=0.f; c[j][1]=0.f; c[j][2]=0.f; c[j][3]=0.f; }

    const __half* bG = g_WhT + kBase;

    auto load_stage = [&](int st, int kc) {
        #pragma unroll
        for (int it = 0; it < 4; it++) {
            int idx = tid + it * GTHR;
            if (idx < 800) {
                int n = idx >> 3, g = idx & 7;
                cpa16(s2u(Bs + st * 104 * BSTR + n * BSTR + g * 8),
                      bG + (size_t)n * VV + kc + g * 8);
            }
        }
        #pragma unroll
        for (int it = 0; it < 4; it++) {
            int idx = tid + it * GTHR;
            int r = idx >> 3, g = idx & 7;
            cpa16(s2u(As + st * MT * ASTR + r * ASTR + g * 8),
                  g_wscr + (size_t)sRow[r] * VV + kBase + kc + g * 8);
        }
        CP_COMMIT();
    };

    load_stage(0, 0);
    int s = 0;
    for (int kc = 0; kc < GKSEG; kc += GKT, s ^= 1) {
        if (kc + GKT < GKSEG) load_stage(s ^ 1, kc + GKT);
        else CP_COMMIT();
        CP_WAIT1();
        __syncthreads();

        const __half* Ab = As + s * MT * ASTR;
        const __half* Bb = Bs + s * 104 * BSTR;
        const int wrow = wid * 16;
        #pragma unroll
        for (int kh = 0; kh < 2; kh++) {
            const int ar = wrow + (lane & 7) + (lane & 8);
            const int ac = kh * 32 + ((lane >> 4) << 3);
            uint32_t a0[4], a1[4];
            ldsm4(a0, s2u(Ab + ar * ASTR + ac));
            ldsm4(a1, s2u(Ab + ar * ASTR + ac + 16));
            const int bc = kh * 32 + ((lane >> 3) << 3);
            #pragma unroll
            for (int j = 0; j < 13; j++) {
                uint32_t b[4];
                ldsm4(b, s2u(Bb + (j * 8 + (lane & 7)) * BSTR + bc));
                mma16816(c[j], a0, b[0], b[1]);
                mma16816(c[j], a1, b[2], b[3]);
            }
        }
        __syncthreads();
    }

    // epilogue: scatter with per-(row,seg) scale
    const int sseg = blockIdx.y / 5;   // 640*5 = 3200 = stats segment
    const int sl0 = wid * 16 + grp;
    const int sl1 = sl0 + 8;
    float s0 = 0.f, s1 = 0.f;
    int r0 = 0, r1 = 0;
    if (rowBase + sl0 < nm) { r0 = sRow[sl0]; s0 = g_scale[r0 * NSEG + sseg]; }
    if (rowBase + sl1 < nm) { r1 = sRow[sl1]; s1 = g_scale[r1 * NSEG + sseg]; }
    #pragma unroll
    for (int j = 0; j < 13; j++) {
        int col = j * 8 + tig * 2;
        if (col < DD) {
            if (s0 != 0.f) atomicAdd(&out_emb[(size_t)r0 * DD + col], c[j][0] * s0);
            if (s1 != 0.f) atomicAdd(&out_emb[(size_t)r1 * DD + col], c[j][2] * s1);
        }
        if (col + 1 < DD) {
            if (s0 != 0.f) atomicAdd(&out_emb[(size_t)r0 * DD + col + 1], c[j][1] * s0);
            if (s1 != 0.f) atomicAdd(&out_emb[(size_t)r1 * DD + col + 1], c[j][3] * s1);
        }
    }
}

// ======== kernel 4: entropy loss reduction ========
__global__ void k_ent(const int* __restrict__ obf_mask, float* __restrict__ out)
{
    __shared__ float ss[256];
    __shared__ int   sc[256];
    const int tid = threadIdx.x;
    float s = 0.f; int c = 0;
    for (int i = tid; i < PP; i += 256) { s += g_ent[i]; c += obf_mask[i]; }
    ss[tid] = s; sc[tid] = c;
    __syncthreads();
    for (int o = 128; o; o >>= 1) {
        if (tid < o) { ss[tid] += ss[tid + o]; sc[tid] += sc[tid + o]; }
        __syncthreads();
    }
    if (tid == 0) {
        float n = (float)sc[0];
        out[PP + (size_t)PP * DD] = ss[0] / (n * (float)VV);
    }
}

// ======== launch ========
extern "C" void kernel_launch(void* const* d_in, const int* in_sizes, int n_in,
                              void* d_out, int out_size)
{
    (void)in_sizes; (void)n_in; (void)out_size;
    const float* logits = (const float*)d_in[0];
    const float* gumb   = (const float*)d_in[1];
    const int*   inp    = (const int*)d_in[2];
    const int*   mask   = (const int*)d_in[3];
    const float* W      = (const float*)d_in[4];
    float* out = (float*)d_out;

    static bool attr_set = false;
    if (!attr_set) {
        cudaFuncSetAttribute(k_gemm, cudaFuncAttributeMaxDynamicSharedMemorySize, GSMEM);
        attr_set = true;
    }

    k_wconv<<<VV / TK, 256>>>(W);
    k_scan<<<1, 1024>>>(mask);
    dim3 gs(PP, NSEG);
    k_stats<<<gs, NT1>>>(logits, gumb, mask);
    k_comb<<<PP / 8, 256>>>(inp, mask, W, out);
    dim3 gg(PP / MT, GNSPLIT);
    k_gemm<<<gg, GTHR, GSMEM>>>(out);
    k_ent<<<1, 256>>>(mask, out);
}

// round 8
// speedup vs baseline: 2.1321x; 1.0102x over previous
#include <cuda_runtime.h>
#include <cuda_fp16.h>
#include <cstdint>

#define PP 2048
#define VV 32000
#define DD 100
#define NT1 256
#define NSEG 10
#define SEGV (VV / NSEG)          // 3200

// ---- static device scratch (no dynamic allocation allowed) ----
__device__ __align__(16) __half g_wscr[(size_t)PP * VV];   // exp(z - mz_seg), fp16
__device__ __align__(16) __half g_WhT[(size_t)DD * VV];    // W transposed, fp16
__device__ float4 g_stA[PP * NSEG];    // (m1, e1, a1, -)
__device__ float4 g_stB[PP * NSEG];    // (mz, e2, ai_bits, -)
__device__ float g_scale[PP * NSEG];   // exp(mz_seg - MZ)/Z2, or 0 if row inactive
__device__ float g_ent[PP];
__device__ int   g_rows[PP];           // compacted masked-row indices
__device__ int   g_nmask;

// -log(u + 1e-20), accurate near u==1 (where __logf's absolute error would
// corrupt the gumbel tail / argmax). Series uses exact d = 1-u for u >= 0.75.
__device__ __forceinline__ float neglog_u(float u) {
    float ue = u + 1e-20f;
    float d = 1.0f - ue;
    float s = d * (1.0f + d * (0.5f + d * (0.33333333f + d * (0.25f + d * (0.2f
             + d * (0.16666667f + d * (0.14285714f + d * (0.125f
             + d * 0.11111111f))))))));
    float l = -__logf(ue);
    return (ue >= 0.75f) ? s : l;
}
__device__ __forceinline__ float gumbel_g(float u) {
    return -__logf(neglog_u(u) + 1e-20f);
}

// ======== kernel 0: W transpose->f16  +  masked-row scan (block 0) ========
#define TK 64
__global__ void k_wconv(const float* __restrict__ W, const int* __restrict__ mask) {
    __shared__ float s[TK][DD + 1];
    const int k0 = blockIdx.x * TK;
    const int tid = threadIdx.x;
    for (int idx = tid; idx < TK * DD; idx += 256) {
        int r = idx / DD, d = idx - r * DD;
        s[r][d] = W[(size_t)(k0 + r) * DD + d];
    }
    __syncthreads();
    for (int idx = tid; idx < TK * DD; idx += 256) {
        int d = idx >> 6, r = idx & 63;
        g_WhT[(size_t)d * VV + k0 + r] = __float2half(s[r][d]);
    }
    if (blockIdx.x == 0) {
        // deterministic compaction scan: 256 threads x 8 masks each
        __shared__ int sp[256];
        int m[8], loc = 0;
        #pragma unroll
        for (int j = 0; j < 8; j++) { m[j] = mask[tid * 8 + j]; loc += m[j]; }
        sp[tid] = loc;
        __syncthreads();
        for (int off = 1; off < 256; off <<= 1) {
            int v = (tid >= off) ? sp[tid - off] : 0;
            __syncthreads();
            sp[tid] += v;
            __syncthreads();
        }
        int excl = sp[tid] - loc;
        #pragma unroll
        for (int j = 0; j < 8; j++)
            if (m[j]) g_rows[excl++] = tid * 8 + j;
        if (tid == 255) g_nmask = sp[255];
    }
}

// ======== kernel 1: per-(row,segment) stats, single memory pass ========
// Each thread owns 16 elements as two 8-element contiguous chunks:
//   chunk A at float4 idx {2t, 2t+1}, chunk B at {512+2t, 513+2t} (t<144).
__global__ void k_stats(const float* __restrict__ logits,
                        const float* __restrict__ gumb,
                        const int* __restrict__ obf_mask)
{
    const int pos = blockIdx.x;
    if (!obf_mask[pos]) return;
    const int seg = blockIdx.y;
    const int tid = threadIdx.x;
    const int base = seg * SEGV;
    const float4* x4 = (const float4*)(logits + (size_t)pos * VV + base);
    const float4* u4 = (const float4*)(gumb   + (size_t)pos * VV + base);

    const int iA = 2 * tid;
    const int iB = 512 + 2 * tid;
    const bool vB = (tid < 144);

    float4 XV[4], UV[4];
    XV[0] = __ldcs(x4 + iA);     XV[1] = __ldcs(x4 + iA + 1);
    UV[0] = __ldcs(u4 + iA);     UV[1] = __ldcs(u4 + iA + 1);
    if (vB) {
        XV[2] = __ldcs(x4 + iB); XV[3] = __ldcs(x4 + iB + 1);
        UV[2] = __ldcs(u4 + iB); UV[3] = __ldcs(u4 + iB + 1);
    } else {
        XV[2] = make_float4(-3.0e38f, -3.0e38f, -3.0e38f, -3.0e38f);
        XV[3] = XV[2];
        UV[2] = make_float4(0.5f, 0.5f, 0.5f, 0.5f);
        UV[3] = UV[2];
    }

    float x[16], z[16];
    float m1 = -3.0e38f, mz = -3.0e38f;
    int ai = 0;
    #pragma unroll
    for (int j = 0; j < 4; j++) {
        const int e0 = base + ((j < 2) ? (iA + j) : (iB + j - 2)) * 4;
        const float* xe = &XV[j].x;
        const float* ue = &UV[j].x;
        #pragma unroll
        for (int e = 0; e < 4; e++) {
            float xv = xe[e];
            float zv = xv + gumbel_g(ue[e]);
            x[j*4+e] = xv; z[j*4+e] = zv;
            m1 = fmaxf(m1, xv);
            if (zv > mz) { mz = zv; ai = e0 + e; }
        }
    }
    const unsigned FULL = 0xffffffffu;
    #pragma unroll
    for (int off = 16; off; off >>= 1) {
        m1 = fmaxf(m1, __shfl_down_sync(FULL, m1, off));
        float oz = __shfl_down_sync(FULL, mz, off);
        int   oi = __shfl_down_sync(FULL, ai, off);
        if (oz > mz || (oz == mz && oi < ai)) { mz = oz; ai = oi; }
    }
    __shared__ float sA[8], sB[8];
    __shared__ int   sI[8];
    const int wid = tid >> 5, lane = tid & 31;
    if (lane == 0) { sA[wid] = m1; sB[wid] = mz; sI[wid] = ai; }
    __syncthreads();
    if (tid == 0) {
        #pragma unroll
        for (int w = 1; w < 8; w++) {
            m1 = fmaxf(m1, sA[w]);
            if (sB[w] > mz || (sB[w] == mz && sI[w] < ai)) { mz = sB[w]; ai = sI[w]; }
        }
        sA[0] = m1; sB[0] = mz; sI[0] = ai;
    }
    __syncthreads();
    const float M1 = sA[0], MZ = sB[0];
    const int   AI = sI[0];
    __syncthreads();

    float e1 = 0.f, a1 = 0.f, e2 = 0.f;
    __half* wr = g_wscr + (size_t)pos * VV + base;
    {   // chunk A (all threads)
        float w[8];
        #pragma unroll
        for (int q = 0; q < 8; q++) {
            float t = x[q] - M1;
            float p = __expf(t);
            e1 += p; a1 += p * t;
            w[q] = __expf(z[q] - MZ);
            e2 += w[q];
        }
        __half2 h0 = __floats2half2_rn(w[0], w[1]);
        __half2 h1 = __floats2half2_rn(w[2], w[3]);
        __half2 h2 = __floats2half2_rn(w[4], w[5]);
        __half2 h3 = __floats2half2_rn(w[6], w[7]);
        uint4 pk;
        pk.x = *(uint32_t*)&h0; pk.y = *(uint32_t*)&h1;
        pk.z = *(uint32_t*)&h2; pk.w = *(uint32_t*)&h3;
        __stcs((uint4*)(wr + iA * 4), pk);
    }
    {   // chunk B (tid<144 stores; invalid lanes contribute exact zeros)
        float w[8];
        #pragma unroll
        for (int q = 8; q < 16; q++) {
            float t = x[q] - M1;
            float p = __expf(t);
            e1 += p; a1 += p * t;
            w[q-8] = __expf(z[q] - MZ);
            e2 += w[q-8];
        }
        if (vB) {
            __half2 h0 = __floats2half2_rn(w[0], w[1]);
            __half2 h1 = __floats2half2_rn(w[2], w[3]);
            __half2 h2 = __floats2half2_rn(w[4], w[5]);
            __half2 h3 = __floats2half2_rn(w[6], w[7]);
            uint4 pk;
            pk.x = *(uint32_t*)&h0; pk.y = *(uint32_t*)&h1;
            pk.z = *(uint32_t*)&h2; pk.w = *(uint32_t*)&h3;
            __stcs((uint4*)(wr + iB * 4), pk);
        }
    }
    #pragma unroll
    for (int off = 16; off; off >>= 1) {
        e1 += __shfl_down_sync(FULL, e1, off);
        a1 += __shfl_down_sync(FULL, a1, off);
        e2 += __shfl_down_sync(FULL, e2, off);
    }
    __shared__ float sE1[8], sA1[8], sE2[8];
    if (lane == 0) { sE1[wid] = e1; sA1[wid] = a1; sE2[wid] = e2; }
    __syncthreads();
    if (tid == 0) {
        float E1 = 0.f, A1 = 0.f, E2 = 0.f;
        #pragma unroll
        for (int w2 = 0; w2 < 8; w2++) { E1 += sE1[w2]; A1 += sA1[w2]; E2 += sE2[w2]; }
        const int idx = pos * NSEG + seg;
        g_stA[idx] = make_float4(M1, E1, A1, 0.f);
        g_stB[idx] = make_float4(MZ, E2, __int_as_float(AI), 0.f);
    }
}

// ======== kernel 2: per-row combine (1 warp/row) ========
__global__ void k_comb(const int* __restrict__ inp_word,
                       const int* __restrict__ obf_mask,
                       const float* __restrict__ W,
                       float* __restrict__ out)
{
    const int row = blockIdx.x * 8 + (threadIdx.x >> 5);
    const int lane = threadIdx.x & 31;
    const unsigned FULL = 0xffffffffu;
    float* out_word = out;
    float* out_emb  = out + PP;
    const int iw = inp_word[row];
    const int mk = obf_mask[row];

    if (!mk) {
        if (lane == 0) { out_word[row] = (float)iw; g_ent[row] = 0.0f; }
        if (lane < NSEG) g_scale[row * NSEG + lane] = 0.0f;
        for (int d = lane; d < DD; d += 32)
            out_emb[(size_t)row * DD + d] = W[(size_t)iw * DD + d];
        return;
    }

    const bool v = lane < NSEG;
    const int idx = row * NSEG + lane;
    float4 pa = v ? g_stA[idx] : make_float4(-3.0e38f, 0.f, 0.f, 0.f);
    float4 pb = v ? g_stB[idx] : make_float4(-3.0e38f, 0.f, __int_as_float(0x7fffffff), 0.f);
    float m1 = pa.x, e1 = pa.y, a1 = pa.z;
    float mz = pb.x, e2 = pb.y;
    int   ai = __float_as_int(pb.z);

    float M1 = m1, MZ = mz; int AI = ai;
    #pragma unroll
    for (int off = 16; off; off >>= 1) {
        M1 = fmaxf(M1, __shfl_xor_sync(FULL, M1, off));
        float omz = __shfl_xor_sync(FULL, MZ, off);
        int   oai = __shfl_xor_sync(FULL, AI, off);
        if (omz > MZ || (omz == MZ && oai < AI)) { MZ = omz; AI = oai; }
    }
    float E1 = v ? e1 * expf(m1 - M1) : 0.f;
    float A1 = v ? (a1 + (m1 - M1) * e1) * expf(m1 - M1) : 0.f;
    float E2 = v ? e2 * expf(mz - MZ) : 0.f;
    #pragma unroll
    for (int off = 16; off; off >>= 1) {
        E1 += __shfl_xor_sync(FULL, E1, off);
        A1 += __shfl_xor_sync(FULL, A1, off);
        E2 += __shfl_xor_sync(FULL, E2, off);
    }
    const int safe = (AI != iw) ? 1 : 0;
    if (lane == 0) {
        g_ent[row] = A1 / E1 - logf(E1);
        out_word[row] = safe ? (float)AI : 0.0f;   // UNK_ID = 0
    }
    if (v) g_scale[idx] = safe ? (expf(mz - MZ) / E2) : 0.0f;
    for (int d = lane; d < DD; d += 32)
        out_emb[(size_t)row * DD + d] = safe ? 0.0f : W[d];
}

// ======== kernel 3: fp16 tensor-core GEMM on compacted rows ========
#define MT 64
#define GKT 64
#define GNSPLIT 20
#define GKSEG (VV / GNSPLIT)   // 1600
#define GTHR 128

__device__ __forceinline__ uint32_t s2u(const void* p) {
    return (uint32_t)__cvta_generic_to_shared(p);
}
__device__ __forceinline__ void ldsm4(uint32_t* r, uint32_t a) {
    asm volatile("ldmatrix.sync.aligned.m8n8.x4.shared.b16 {%0,%1,%2,%3},[%4];"
        : "=r"(r[0]), "=r"(r[1]), "=r"(r[2]), "=r"(r[3]) : "r"(a));
}
__device__ __forceinline__ void mma16816(float* c, const uint32_t* a,
                                         uint32_t b0, uint32_t b1) {
    asm volatile("mma.sync.aligned.m16n8k16.row.col.f32.f16.f16.f32 "
        "{%0,%1,%2,%3},{%4,%5,%6,%7},{%8,%9},{%0,%1,%2,%3};"
        : "+f"(c[0]), "+f"(c[1]), "+f"(c[2]), "+f"(c[3])
        : "r"(a[0]), "r"(a[1]), "r"(a[2]), "r"(a[3]), "r"(b0), "r"(b1));
}
__device__ __forceinline__ void cpa16(uint32_t s, const void* g) {
    asm volatile("cp.async.cg.shared.global [%0], [%1], 16;" :: "r"(s), "l"(g));
}
#define CP_COMMIT() asm volatile("cp.async.commit_group;")
#define CP_WAIT1()  asm volatile("cp.async.wait_group 1;")

#define ASTR 72
#define BSTR 72

__global__ void __launch_bounds__(GTHR, 4) k_gemm(float* __restrict__ out)
{
    const int nm = g_nmask;
    const int rowBase = blockIdx.x * MT;
    if (rowBase >= nm) return;

    __shared__ __align__(16) __half As[2][MT * ASTR];
    __shared__ __align__(16) __half Bs[2][104 * BSTR];
    __shared__ int sRow[MT];

    float* out_emb = out + PP;
    const int kBase = blockIdx.y * GKSEG;
    const int tid = threadIdx.x;
    const int wid = tid >> 5, lane = tid & 31;
    const int grp = lane >> 2, tig = lane & 3;

    if (tid < MT) {
        int slot = rowBase + tid;
        sRow[tid] = g_rows[(slot < nm) ? slot : 0];
    }
    // zero B pad rows 100..103, both stages (36 u32 per row)
    for (int i = tid; i < 288; i += GTHR) {
        int st = i / 144, rem = i % 144;
        int r = rem / 36, c2 = rem % 36;
        ((uint32_t*)(Bs[st] + (100 + r) * BSTR))[c2] = 0u;
    }
    __syncthreads();

    float c[13][4];
    #pragma unroll
    for (int j = 0; j < 13; j++) { c[j][0]=0.f; c[j][1]=0.f; c[j][2]=0.f; c[j][3]=0.f; }

    const __half* bG = g_WhT + kBase;

    auto load_stage = [&](int st, int kc) {
        #pragma unroll
        for (int it = 0; it < 7; it++) {
            int idx = tid + it * GTHR;
            if (idx < 800) {
                int n = idx >> 3, g = idx & 7;
                cpa16(s2u(Bs[st] + n * BSTR + g * 8),
                      bG + (size_t)n * VV + kc + g * 8);
            }
        }
        #pragma unroll
        for (int it = 0; it < 4; it++) {
            int idx = tid + it * GTHR;
            int r = idx >> 3, g = idx & 7;
            cpa16(s2u(As[st] + r * ASTR + g * 8),
                  g_wscr + (size_t)sRow[r] * VV + kBase + kc + g * 8);
        }
        CP_COMMIT();
    };

    load_stage(0, 0);
    int s = 0;
    for (int kc = 0; kc < GKSEG; kc += GKT, s ^= 1) {
        if (kc + GKT < GKSEG) load_stage(s ^ 1, kc + GKT);
        else CP_COMMIT();
        CP_WAIT1();
        __syncthreads();

        const int wrow = wid * 16;
        #pragma unroll
        for (int kh = 0; kh < 2; kh++) {
            const int ar = wrow + (lane & 7) + (lane & 8);
            const int ac = kh * 32 + ((lane >> 4) << 3);
            uint32_t a0[4], a1[4];
            ldsm4(a0, s2u(As[s] + ar * ASTR + ac));
            ldsm4(a1, s2u(As[s] + ar * ASTR + ac + 16));
            const int bc = kh * 32 + ((lane >> 3) << 3);
            #pragma unroll
            for (int j = 0; j < 13; j++) {
                uint32_t b[4];
                ldsm4(b, s2u(Bs[s] + (j * 8 + (lane & 7)) * BSTR + bc));
                mma16816(c[j], a0, b[0], b[1]);
                mma16816(c[j], a1, b[2], b[3]);
            }
        }
        __syncthreads();
    }

    // epilogue: scatter with per-(row,seg) scale
    const int sseg = blockIdx.y >> 1;   // 1600*2 = 3200 = stats segment
    const int sl0 = wid * 16 + grp;
    const int sl1 = sl0 + 8;
    float s0 = 0.f, s1 = 0.f;
    int r0 = 0, r1 = 0;
    if (rowBase + sl0 < nm) { r0 = sRow[sl0]; s0 = g_scale[r0 * NSEG + sseg]; }
    if (rowBase + sl1 < nm) { r1 = sRow[sl1]; s1 = g_scale[r1 * NSEG + sseg]; }
    #pragma unroll
    for (int j = 0; j < 13; j++) {
        int col = j * 8 + tig * 2;
        if (col < DD) {
            if (s0 != 0.f) atomicAdd(&out_emb[(size_t)r0 * DD + col], c[j][0] * s0);
            if (s1 != 0.f) atomicAdd(&out_emb[(size_t)r1 * DD + col], c[j][2] * s1);
        }
        if (col + 1 < DD) {
            if (s0 != 0.f) atomicAdd(&out_emb[(size_t)r0 * DD + col + 1], c[j][1] * s0);
            if (s1 != 0.f) atomicAdd(&out_emb[(size_t)r1 * DD + col + 1], c[j][3] * s1);
        }
    }
}

// ======== kernel 4: entropy loss reduction ========
__global__ void k_ent(const int* __restrict__ obf_mask, float* __restrict__ out)
{
    __shared__ float ss[256];
    __shared__ int   sc[256];
    const int tid = threadIdx.x;
    float s = 0.f; int c = 0;
    for (int i = tid; i < PP; i += 256) { s += g_ent[i]; c += obf_mask[i]; }
    ss[tid] = s; sc[tid] = c;
    __syncthreads();
    for (int o = 128; o; o >>= 1) {
        if (tid < o) { ss[tid] += ss[tid + o]; sc[tid] += sc[tid + o]; }
        __syncthreads();
    }
    if (tid == 0) {
        float n = (float)sc[0];
        out[PP + (size_t)PP * DD] = ss[0] / (n * (float)VV);
    }
}

// ======== launch ========
extern "C" void kernel_launch(void* const* d_in, const int* in_sizes, int n_in,
                              void* d_out, int out_size)
{
    (void)in_sizes; (void)n_in; (void)out_size;
    const float* logits = (const float*)d_in[0];
    const float* gumb   = (const float*)d_in[1];
    const int*   inp    = (const int*)d_in[2];
    const int*   mask   = (const int*)d_in[3];
    const float* W      = (const float*)d_in[4];
    float* out = (float*)d_out;

    k_wconv<<<VV / TK, 256>>>(W, mask);
    dim3 gs(PP, NSEG);
    k_stats<<<gs, NT1>>>(logits, gumb, mask);
    k_comb<<<PP / 8, 256>>>(inp, mask, W, out);
    dim3 gg(PP / MT, GNSPLIT);
    k_gemm<<<gg, GTHR>>>(out);
    k_ent<<<1, 256>>>(mask, out);
}

// round 10
// speedup vs baseline: 2.2649x; 1.0623x over previous
#include <cuda_runtime.h>
#include <cuda_fp16.h>
#include <cstdint>

#define PP 2048
#define VV 32000
#define DD 100
#define NT1 256
#define NSEG 10
#define SEGV (VV / NSEG)          // 3200

#define MT 64
#define GKT 64
#define GNSPLIT 50
#define GKSEG (VV / GNSPLIT)      // 640
#define GTHR 128
#define NSTG 3

// ---- static device scratch (no dynamic allocation allowed) ----
__device__ __align__(16) __half g_wscr[(size_t)PP * VV];   // exp(z - mz_seg), fp16
__device__ __align__(16) __half g_WhT[(size_t)DD * VV];    // W transposed, fp16
__device__ __align__(16) float  g_part[GNSPLIT][PP][104];  // GEMM k-split partials
__device__ float4 g_stA[PP * NSEG];    // (m1, e1, a1, -)
__device__ float4 g_stB[PP * NSEG];    // (mz, e2, ai_bits, -)
__device__ float g_scale[PP * NSEG];   // exp(mz_seg - MZ)/Z2, or 0 if row inactive
__device__ float g_ent[PP];
__device__ int   g_rows[PP];           // compacted masked-row indices
__device__ int   g_safe[PP];
__device__ int   g_nmask;

// -log(u + 1e-20), accurate near u==1 (where __logf's absolute error would
// corrupt the gumbel tail / argmax). Series uses exact d = 1-u for u >= 0.75.
__device__ __forceinline__ float neglog_u(float u) {
    float ue = u + 1e-20f;
    float d = 1.0f - ue;
    float s = d * (1.0f + d * (0.5f + d * (0.33333333f + d * (0.25f + d * (0.2f
             + d * (0.16666667f + d * (0.14285714f + d * (0.125f
             + d * 0.11111111f))))))));
    float l = -__logf(ue);
    return (ue >= 0.75f) ? s : l;
}
__device__ __forceinline__ float gumbel_g(float u) {
    return -__logf(neglog_u(u) + 1e-20f);
}

// ======== kernel 0: W transpose->f16  +  masked-row scan (block 0) ========
#define TK 64
__global__ void k_wconv(const float* __restrict__ W, const int* __restrict__ mask) {
    __shared__ float s[TK][DD + 1];
    const int k0 = blockIdx.x * TK;
    const int tid = threadIdx.x;
    for (int idx = tid; idx < TK * DD; idx += 256) {
        int r = idx / DD, d = idx - r * DD;
        s[r][d] = W[(size_t)(k0 + r) * DD + d];
    }
    __syncthreads();
    for (int idx = tid; idx < TK * DD; idx += 256) {
        int d = idx >> 6, r = idx & 63;
        g_WhT[(size_t)d * VV + k0 + r] = __float2half(s[r][d]);
    }
    if (blockIdx.x == 0) {
        __shared__ int sp[256];
        int m[8], loc = 0;
        #pragma unroll
        for (int j = 0; j < 8; j++) { m[j] = mask[tid * 8 + j]; loc += m[j]; }
        sp[tid] = loc;
        __syncthreads();
        for (int off = 1; off < 256; off <<= 1) {
            int v = (tid >= off) ? sp[tid - off] : 0;
            __syncthreads();
            sp[tid] += v;
            __syncthreads();
        }
        int excl = sp[tid] - loc;
        #pragma unroll
        for (int j = 0; j < 8; j++)
            if (m[j]) g_rows[excl++] = tid * 8 + j;
        if (tid == 255) g_nmask = sp[255];
    }
}

// ======== kernel 1: per-(row,segment) stats, single memory pass ========
__global__ void k_stats(const float* __restrict__ logits,
                        const float* __restrict__ gumb,
                        const int* __restrict__ obf_mask)
{
    const int pos = blockIdx.x;
    if (!obf_mask[pos]) return;
    const int seg = blockIdx.y;
    const int tid = threadIdx.x;
    const int base = seg * SEGV;
    const float4* x4 = (const float4*)(logits + (size_t)pos * VV + base);
    const float4* u4 = (const float4*)(gumb   + (size_t)pos * VV + base);

    const int iA = 2 * tid;
    const int iB = 512 + 2 * tid;
    const bool vB = (tid < 144);

    float4 XV[4], UV[4];
    XV[0] = __ldcs(x4 + iA);     XV[1] = __ldcs(x4 + iA + 1);
    UV[0] = __ldcs(u4 + iA);     UV[1] = __ldcs(u4 + iA + 1);
    if (vB) {
        XV[2] = __ldcs(x4 + iB); XV[3] = __ldcs(x4 + iB + 1);
        UV[2] = __ldcs(u4 + iB); UV[3] = __ldcs(u4 + iB + 1);
    } else {
        XV[2] = make_float4(-3.0e38f, -3.0e38f, -3.0e38f, -3.0e38f);
        XV[3] = XV[2];
        UV[2] = make_float4(0.5f, 0.5f, 0.5f, 0.5f);
        UV[3] = UV[2];
    }

    float x[16], z[16];
    float m1 = -3.0e38f, mz = -3.0e38f;
    int ai = 0;
    #pragma unroll
    for (int j = 0; j < 4; j++) {
        const int e0 = base + ((j < 2) ? (iA + j) : (iB + j - 2)) * 4;
        const float* xe = &XV[j].x;
        const float* ue = &UV[j].x;
        #pragma unroll
        for (int e = 0; e < 4; e++) {
            float xv = xe[e];
            float zv = xv + gumbel_g(ue[e]);
            x[j*4+e] = xv; z[j*4+e] = zv;
            m1 = fmaxf(m1, xv);
            if (zv > mz) { mz = zv; ai = e0 + e; }
        }
    }
    const unsigned FULL = 0xffffffffu;
    #pragma unroll
    for (int off = 16; off; off >>= 1) {
        m1 = fmaxf(m1, __shfl_down_sync(FULL, m1, off));
        float oz = __shfl_down_sync(FULL, mz, off);
        int   oi = __shfl_down_sync(FULL, ai, off);
        if (oz > mz || (oz == mz && oi < ai)) { mz = oz; ai = oi; }
    }
    __shared__ float sA[8], sB[8];
    __shared__ int   sI[8];
    const int wid = tid >> 5, lane = tid & 31;
    if (lane == 0) { sA[wid] = m1; sB[wid] = mz; sI[wid] = ai; }
    __syncthreads();
    if (tid == 0) {
        #pragma unroll
        for (int w = 1; w < 8; w++) {
            m1 = fmaxf(m1, sA[w]);
            if (sB[w] > mz || (sB[w] == mz && sI[w] < ai)) { mz = sB[w]; ai = sI[w]; }
        }
        sA[0] = m1; sB[0] = mz; sI[0] = ai;
    }
    __syncthreads();
    const float M1 = sA[0], MZ = sB[0];
    const int   AI = sI[0];
    __syncthreads();

    float e1 = 0.f, a1 = 0.f, e2 = 0.f;
    __half* wr = g_wscr + (size_t)pos * VV + base;
    {   // chunk A (all threads)
        float w[8];
        #pragma unroll
        for (int q = 0; q < 8; q++) {
            float t = x[q] - M1;
            float p = __expf(t);
            e1 += p; a1 += p * t;
            w[q] = __expf(z[q] - MZ);
            e2 += w[q];
        }
        __half2 h0 = __floats2half2_rn(w[0], w[1]);
        __half2 h1 = __floats2half2_rn(w[2], w[3]);
        __half2 h2 = __floats2half2_rn(w[4], w[5]);
        __half2 h3 = __floats2half2_rn(w[6], w[7]);
        uint4 pk;
        pk.x = *(uint32_t*)&h0; pk.y = *(uint32_t*)&h1;
        pk.z = *(uint32_t*)&h2; pk.w = *(uint32_t*)&h3;
        *(uint4*)(wr + iA * 4) = pk;    // default policy: keep resident in L2 for GEMM
    }
    {   // chunk B
        float w[8];
        #pragma unroll
        for (int q = 8; q < 16; q++) {
            float t = x[q] - M1;
            float p = __expf(t);
            e1 += p; a1 += p * t;
            w[q-8] = __expf(z[q] - MZ);
            e2 += w[q-8];
        }
        if (vB) {
            __half2 h0 = __floats2half2_rn(w[0], w[1]);
            __half2 h1 = __floats2half2_rn(w[2], w[3]);
            __half2 h2 = __floats2half2_rn(w[4], w[5]);
            __half2 h3 = __floats2half2_rn(w[6], w[7]);
            uint4 pk;
            pk.x = *(uint32_t*)&h0; pk.y = *(uint32_t*)&h1;
            pk.z = *(uint32_t*)&h2; pk.w = *(uint32_t*)&h3;
            *(uint4*)(wr + iB * 4) = pk;
        }
    }
    #pragma unroll
    for (int off = 16; off; off >>= 1) {
        e1 += __shfl_down_sync(FULL, e1, off);
        a1 += __shfl_down_sync(FULL, a1, off);
        e2 += __shfl_down_sync(FULL, e2, off);
    }
    __shared__ float sE1[8], sA1[8], sE2[8];
    if (lane == 0) { sE1[wid] = e1; sA1[wid] = a1; sE2[wid] = e2; }
    __syncthreads();
    if (tid == 0) {
        float E1 = 0.f, A1 = 0.f, E2 = 0.f;
        #pragma unroll
        for (int w2 = 0; w2 < 8; w2++) { E1 += sE1[w2]; A1 += sA1[w2]; E2 += sE2[w2]; }
        const int idx = pos * NSEG + seg;
        g_stA[idx] = make_float4(M1, E1, A1, 0.f);
        g_stB[idx] = make_float4(MZ, E2, __int_as_float(AI), 0.f);
    }
}

// ======== kernel 2: per-row combine (1 warp/row) ========
__global__ void k_comb(const int* __restrict__ inp_word,
                       const int* __restrict__ obf_mask,
                       const float* __restrict__ W,
                       float* __restrict__ out)
{
    const int row = blockIdx.x * 8 + (threadIdx.x >> 5);
    const int lane = threadIdx.x & 31;
    const unsigned FULL = 0xffffffffu;
    float* out_word = out;
    float* out_emb  = out + PP;
    const int iw = inp_word[row];
    const int mk = obf_mask[row];

    if (!mk) {
        if (lane == 0) { out_word[row] = (float)iw; g_ent[row] = 0.0f; g_safe[row] = 0; }
        if (lane < NSEG) g_scale[row * NSEG + lane] = 0.0f;
        for (int d = lane; d < DD; d += 32)
            out_emb[(size_t)row * DD + d] = W[(size_t)iw * DD + d];
        return;
    }

    const bool v = lane < NSEG;
    const int idx = row * NSEG + lane;
    float4 pa = v ? g_stA[idx] : make_float4(-3.0e38f, 0.f, 0.f, 0.f);
    float4 pb = v ? g_stB[idx] : make_float4(-3.0e38f, 0.f, __int_as_float(0x7fffffff), 0.f);
    float m1 = pa.x, e1 = pa.y, a1 = pa.z;
    float mz = pb.x, e2 = pb.y;
    int   ai = __float_as_int(pb.z);

    float M1 = m1, MZ = mz; int AI = ai;
    #pragma unroll
    for (int off = 16; off; off >>= 1) {
        M1 = fmaxf(M1, __shfl_xor_sync(FULL, M1, off));
        float omz = __shfl_xor_sync(FULL, MZ, off);
        int   oai = __shfl_xor_sync(FULL, AI, off);
        if (omz > MZ || (omz == MZ && oai < AI)) { MZ = omz; AI = oai; }
    }
    float E1 = v ? e1 * expf(m1 - M1) : 0.f;
    float A1 = v ? (a1 + (m1 - M1) * e1) * expf(m1 - M1) : 0.f;
    float E2 = v ? e2 * expf(mz - MZ) : 0.f;
    #pragma unroll
    for (int off = 16; off; off >>= 1) {
        E1 += __shfl_xor_sync(FULL, E1, off);
        A1 += __shfl_xor_sync(FULL, A1, off);
        E2 += __shfl_xor_sync(FULL, E2, off);
    }
    const int safe = (AI != iw) ? 1 : 0;
    if (lane == 0) {
        g_ent[row] = A1 / E1 - logf(E1);
        out_word[row] = safe ? (float)AI : 0.0f;   // UNK_ID = 0
        g_safe[row] = safe;
    }
    if (v) g_scale[idx] = safe ? (expf(mz - MZ) / E2) : 0.0f;
    if (!safe)
        for (int d = lane; d < DD; d += 32)
            out_emb[(size_t)row * DD + d] = W[d];   // UNK embedding
    // safe rows: k_red writes all 100 dims
}

// ======== kernel 3: fp16 GEMM, 3-stage cp.async, partial epilogue ========
__device__ __forceinline__ uint32_t s2u(const void* p) {
    return (uint32_t)__cvta_generic_to_shared(p);
}
__device__ __forceinline__ void ldsm4(uint32_t* r, uint32_t a) {
    asm volatile("ldmatrix.sync.aligned.m8n8.x4.shared.b16 {%0,%1,%2,%3},[%4];"
        : "=r"(r[0]), "=r"(r[1]), "=r"(r[2]), "=r"(r[3]) : "r"(a));
}
__device__ __forceinline__ void mma16816(float* c, const uint32_t* a,
                                         uint32_t b0, uint32_t b1) {
    asm volatile("mma.sync.aligned.m16n8k16.row.col.f32.f16.f16.f32 "
        "{%0,%1,%2,%3},{%4,%5,%6,%7},{%8,%9},{%0,%1,%2,%3};"
        : "+f"(c[0]), "+f"(c[1]), "+f"(c[2]), "+f"(c[3])
        : "r"(a[0]), "r"(a[1]), "r"(a[2]), "r"(a[3]), "r"(b0), "r"(b1));
}
__device__ __forceinline__ void cpa16(uint32_t s, const void* g) {
    asm volatile("cp.async.cg.shared.global [%0], [%1], 16;" :: "r"(s), "l"(g));
}
#define CP_COMMIT() asm volatile("cp.async.commit_group;")
#define CP_WAIT2()  asm volatile("cp.async.wait_group 2;")

#define ASTR 72
#define BSTR 72
#define NITER (GKSEG / GKT)    // 10

__global__ void __launch_bounds__(GTHR, 3) k_gemm(void)
{
    const int nm = g_nmask;
    const int rowBase = blockIdx.x * MT;
    if (rowBase >= nm) return;

    __shared__ __align__(16) __half As[NSTG][MT * ASTR];
    __shared__ __align__(16) __half Bs[NSTG][104 * BSTR];
    __shared__ int sRow[MT];

    const int kBase = blockIdx.y * GKSEG;
    const int tid = threadIdx.x;
    const int wid = tid >> 5, lane = tid & 31;
    const int grp = lane >> 2, tig = lane & 3;

    if (tid < MT) {
        int slot = rowBase + tid;
        sRow[tid] = g_rows[(slot < nm) ? slot : 0];
    }
    // zero B pad rows 100..103, all stages (36 u32 per row)
    for (int i = tid; i < NSTG * 144; i += GTHR) {
        int st = i / 144, rem = i % 144;
        int r = rem / 36, c2 = rem % 36;
        ((uint32_t*)(Bs[st] + (100 + r) * BSTR))[c2] = 0u;
    }
    __syncthreads();

    float c[13][4];
    #pragma unroll
    for (int j = 0; j < 13; j++) { c[j][0]=0.f; c[j][1]=0.f; c[j][2]=0.f; c[j][3]=0.f; }

    const __half* bG = g_WhT + kBase;

    auto load_stage = [&](int st, int kc) {
        #pragma unroll
        for (int it = 0; it < 7; it++) {
            int idx = tid + it * GTHR;
            if (idx < 800) {
                int n = idx >> 3, g = idx & 7;
                cpa16(s2u(Bs[st] + n * BSTR + g * 8),
                      bG + (size_t)n * VV + kc + g * 8);
            }
        }
        #pragma unroll
        for (int it = 0; it < 4; it++) {
            int idx = tid + it * GTHR;
            int r = idx >> 3, g = idx & 7;
            cpa16(s2u(As[st] + r * ASTR + g * 8),
                  g_wscr + (size_t)sRow[r] * VV + kBase + kc + g * 8);
        }
        CP_COMMIT();
    };

    load_stage(0, 0);
    load_stage(1, GKT);
    #pragma unroll 1
    for (int i = 0; i < NITER; i++) {
        if (i + 2 < NITER) load_stage((i + 2) % NSTG, (i + 2) * GKT);
        else CP_COMMIT();
        CP_WAIT2();
        __syncthreads();

        const int s = i % NSTG;
        const int wrow = wid * 16;
        #pragma unroll
        for (int kh = 0; kh < 2; kh++) {
            const int ar = wrow + (lane & 7) + (lane & 8);
            const int ac = kh * 32 + ((lane >> 4) << 3);
            uint32_t a0[4], a1[4];
            ldsm4(a0, s2u(As[s] + ar * ASTR + ac));
            ldsm4(a1, s2u(As[s] + ar * ASTR + ac + 16));
            const int bc = kh * 32 + ((lane >> 3) << 3);
            #pragma unroll
            for (int j = 0; j < 13; j++) {
                uint32_t b[4];
                ldsm4(b, s2u(Bs[s] + (j * 8 + (lane & 7)) * BSTR + bc));
                mma16816(c[j], a0, b[0], b[1]);
                mma16816(c[j], a1, b[2], b[3]);
            }
        }
        __syncthreads();
    }

    // epilogue: scale, store partials (no atomics; .cg keeps them out of L1)
    const int sseg = blockIdx.y / 5;   // 640*5 = 3200 = stats segment
    const int sl0 = wid * 16 + grp;
    const int sl1 = sl0 + 8;
    const int r0 = sRow[sl0], r1 = sRow[sl1];
    const float s0 = g_scale[r0 * NSEG + sseg];
    const float s1 = g_scale[r1 * NSEG + sseg];
    float* p0 = &g_part[blockIdx.y][rowBase + sl0][0];
    float* p1 = &g_part[blockIdx.y][rowBase + sl1][0];
    #pragma unroll
    for (int j = 0; j < 13; j++) {
        int col = j * 8 + tig * 2;
        __stcg((float2*)(p0 + col), make_float2(c[j][0] * s0, c[j][1] * s0));
        __stcg((float2*)(p1 + col), make_float2(c[j][2] * s1, c[j][3] * s1));
    }
}

// ======== kernel 3b: reduce k-split partials into out_emb ========
__global__ void k_red(float* __restrict__ out)
{
    const int b = blockIdx.x;
    if (b >= g_nmask) return;
    const int row = g_rows[b];
    if (!g_safe[row]) return;
    const int d = threadIdx.x;
    if (d >= DD) return;
    float acc = 0.f;
    #pragma unroll 10
    for (int s = 0; s < GNSPLIT; s++)
        acc += __ldcg(&g_part[s][b][d]);
    out[PP + (size_t)row * DD + d] = acc;
}

// ======== kernel 4: entropy loss reduction ========
__global__ void k_ent(const int* __restrict__ obf_mask, float* __restrict__ out)
{
    __shared__ float ss[256];
    __shared__ int   sc[256];
    const int tid = threadIdx.x;
    float s = 0.f; int c = 0;
    for (int i = tid; i < PP; i += 256) { s += g_ent[i]; c += obf_mask[i]; }
    ss[tid] = s; sc[tid] = c;
    __syncthreads();
    for (int o = 128; o; o >>= 1) {
        if (tid < o) { ss[tid] += ss[tid + o]; sc[tid] += sc[tid + o]; }
        __syncthreads();
    }
    if (tid == 0) {
        float n = (float)sc[0];
        out[PP + (size_t)PP * DD] = ss[0] / (n * (float)VV);
    }
}

// ======== launch ========
extern "C" void kernel_launch(void* const* d_in, const int* in_sizes, int n_in,
                              void* d_out, int out_size)
{
    (void)in_sizes; (void)n_in; (void)out_size;
    const float* logits = (const float*)d_in[0];
    const float* gumb   = (const float*)d_in[1];
    const int*   inp    = (const int*)d_in[2];
    const int*   mask   = (const int*)d_in[3];
    const float* W      = (const float*)d_in[4];
    float* out = (float*)d_out;

    k_wconv<<<VV / TK, 256>>>(W, mask);
    dim3 gs(PP, NSEG);
    k_stats<<<gs, NT1>>>(logits, gumb, mask);
    k_comb<<<PP / 8, 256>>>(inp, mask, W, out);
    dim3 gg(PP / MT, GNSPLIT);
    k_gemm<<<gg, GTHR>>>();
    k_red<<<PP, 128>>>(out);
    k_ent<<<1, 256>>>(mask, out);
}